// round 10
// baseline (speedup 1.0000x reference)
#include <cuda_runtime.h>
#include <cuda_bf16.h>
#include <cstdint>

// Problem constants
#define Gg 8
#define Nn 1024
#define Ff 128
#define Hh 256
#define Ll 4
#define Bb 64
#define CAP 128

// ---------------- scratch (device globals) ----------------------------------
__device__ __align__(16) float    g_X0 [Gg * Nn * Hh];          // fp32 residual
__device__ __align__(16) uint32_t g_X0b[Gg * Nn * Hh / 2];      // bf16x2 copy of X0
__device__ __align__(16) float    g_X  [Gg * Nn * Hh];          // fp32 final x
__device__ __align__(16) uint32_t g_Xb [Gg * Nn * Hh / 2];      // bf16x2 inter-layer x
__device__ __align__(16) uint32_t g_Yb [Gg * Nn * Hh / 2];      // bf16x2 Y = x @ W
__device__ __align__(16) uint32_t g_Wtb[Ll * Hh * Hh / 2];      // bf16x2 Ws^T [l][n][k]
__device__ __align__(16) float    g_WtIn[Hh * Ff];              // W_in^T (tf32-rounded)
__device__ unsigned short g_cols[(long)Gg * Nn * CAP];
__device__ __align__(16) float g_vals[(long)Gg * Nn * CAP];
__device__ int   g_nnz[Gg * Nn];
__device__ float g_maskf[Bb * Nn];
__device__ float g_cnt[Bb];

// ---------------- helpers ----------------------------------------------------
__device__ __forceinline__ float f2tf32(float x) {
    uint32_t r;
    asm("cvt.rna.tf32.f32 %0, %1;" : "=r"(r) : "f"(x));
    return __uint_as_float(r);
}
__device__ __forceinline__ uint32_t frag_tf32(float x) {
    uint32_t r;
    asm("cvt.rna.tf32.f32 %0, %1;" : "=r"(r) : "f"(x));
    return r;
}

__device__ __forceinline__ void mma_tf32(float& c0, float& c1, float& c2, float& c3,
                                         uint32_t a0, uint32_t a1, uint32_t a2, uint32_t a3,
                                         uint32_t b0, uint32_t b1) {
    asm volatile(
        "mma.sync.aligned.m16n8k8.row.col.f32.tf32.tf32.f32 "
        "{%0,%1,%2,%3}, {%4,%5,%6,%7}, {%8,%9}, {%0,%1,%2,%3};"
        : "+f"(c0), "+f"(c1), "+f"(c2), "+f"(c3)
        : "r"(a0), "r"(a1), "r"(a2), "r"(a3), "r"(b0), "r"(b1));
}
__device__ __forceinline__ void mma_bf16(float& c0, float& c1, float& c2, float& c3,
                                         uint32_t a0, uint32_t a1, uint32_t a2, uint32_t a3,
                                         uint32_t b0, uint32_t b1) {
    asm volatile(
        "mma.sync.aligned.m16n8k16.row.col.f32.bf16.bf16.f32 "
        "{%0,%1,%2,%3}, {%4,%5,%6,%7}, {%8,%9}, {%0,%1,%2,%3};"
        : "+f"(c0), "+f"(c1), "+f"(c2), "+f"(c3)
        : "r"(a0), "r"(a1), "r"(a2), "r"(a3), "r"(b0), "r"(b1));
}

__device__ __forceinline__ void cp16(void* dst_smem, const void* src) {
    uint32_t d = (uint32_t)__cvta_generic_to_shared(dst_smem);
    asm volatile("cp.async.cg.shared.global [%0], [%1], 16;"
                 :: "r"(d), "l"(src) : "memory");
}
#define CP_COMMIT() asm volatile("cp.async.commit_group;" ::: "memory")
#define CP_WAIT2()  asm volatile("cp.async.wait_group 2;" ::: "memory")
#define CP_WAIT1()  asm volatile("cp.async.wait_group 1;" ::: "memory")
#define CP_WAIT0()  asm volatile("cp.async.wait_group 0;" ::: "memory")

// detect mask dtype from the first 1024 words (deterministic, identical
// for every block: col 0 of every row is forced True by the reference).
__device__ __forceinline__ int detect_mode_local(const unsigned int* m) {
    int f = 0, b = 0;
    for (int i = 0; i < 1024; i += 8) {
        #pragma unroll
        for (int q = 0; q < 8; q++) {
            unsigned int w = m[i + q];
            if (w == 0x3F800000u) f = 1;
            if (w > 1u && (w & ~0x01010101u) == 0u) b = 1;
        }
        if (f | b) break;
    }
    return f ? 1 : (b ? 2 : 0);
}

// ---------------- merged prep + CSR + mask -----------------------------------
// grid.x layout (256 threads each):
//   [0, Gg*Nn)           : CSR row build
//   [Gg*Nn, +Bb)         : mask expand (self-detected dtype) + zero d_out row
//   [Gg*Nn+Bb, +320)     : weight transposes (z = idx/64: 0..3 Ws->bf16, 4 W_in)
#define CSR_BLKS (Gg * Nn)
#define PREP_BLKS (CSR_BLKS + Bb + 320)
__global__ void csr_mask_prep_kernel(const float* __restrict__ Adj,
                                     const void* __restrict__ mraw,
                                     float* __restrict__ out,
                                     const float* __restrict__ Ws,
                                     const float* __restrict__ W_in) {
    const int bid = blockIdx.x;
    const int t = threadIdx.x;

    if (bid < CSR_BLKS) {
        long rbase = bid;   // g * Nn + n
        const float* row = Adj + rbase * Nn;
        __shared__ int cnt;
        if (t == 0) cnt = 0;
        __syncthreads();
        for (int m = t; m < Nn; m += 256) {
            float v = row[m];
            if (v != 0.0f) {
                int p = atomicAdd(&cnt, 1);
                if (p < CAP) {
                    g_cols[rbase * CAP + p] = (unsigned short)m;
                    g_vals[rbase * CAP + p] = v;
                }
            }
        }
        __syncthreads();
        if (t == 0) g_nnz[rbase] = cnt < CAP ? cnt : CAP;
        return;
    }

    if (bid < CSR_BLKS + Bb) {
        int b = bid - CSR_BLKS;
        out[(long)b * 256 + t] = 0.0f;   // zero d_out row
        int mode = detect_mode_local((const unsigned int*)mraw);
        __shared__ int cnt;
        if (t == 0) cnt = 0;
        __syncthreads();
        int local = 0;
        for (int n = t; n < Nn; n += 256) {
            long idx = (long)b * Nn + n;
            bool on;
            if (mode == 1)      on = ((const float*)mraw)[idx] != 0.0f;
            else if (mode == 2) on = ((const unsigned char*)mraw)[idx] != 0;
            else                on = ((const int*)mraw)[idx] != 0;
            g_maskf[idx] = on ? 1.0f : 0.0f;
            local += on ? 1 : 0;
        }
        atomicAdd(&cnt, local);
        __syncthreads();
        if (t == 0) g_cnt[b] = (float)(cnt < 1 ? 1 : cnt);
        return;
    }

    // transpose section (32x8 logical layout inside 256 threads)
    __shared__ float tile[32][33];
    int idx = bid - CSR_BLKS - Bb;
    int z = idx >> 6;           // 0..4
    int rem = idx & 63;
    int bx = rem & 7, by = rem >> 3;
    int x = t & 31, y = t >> 5;

    if (z < Ll) {
        const float* src = Ws + (long)z * Hh * Hh;
        __nv_bfloat16* dst = reinterpret_cast<__nv_bfloat16*>(g_Wtb) + (long)z * Hh * Hh;
        int k0 = bx * 32, h0 = by * 32;
        #pragma unroll
        for (int j = 0; j < 32; j += 8)
            tile[y + j][x] = src[(long)(k0 + y + j) * Hh + h0 + x];
        __syncthreads();
        #pragma unroll
        for (int j = 0; j < 32; j += 8)
            dst[(long)(h0 + y + j) * Hh + k0 + x] = __float2bfloat16(tile[x][y + j]);
    } else {
        if (bx >= Ff / 32) return;
        int k0 = bx * 32, h0 = by * 32;
        #pragma unroll
        for (int j = 0; j < 32; j += 8)
            tile[y + j][x] = W_in[(long)(k0 + y + j) * Hh + h0 + x];
        __syncthreads();
        #pragma unroll
        for (int j = 0; j < 32; j += 8)
            g_WtIn[(long)(h0 + y + j) * Ff + k0 + x] = f2tf32(tile[x][y + j]);
    }
}

// ---------------- tf32 input GEMM (fp32 A), 4-stage, 128x64 ------------------
// X0 = relu(xs @ W_in^T + b_in), writes fp32 X0 AND bf16 copy X0b.
#define APITCH 36
#define ABUF (128 * APITCH)
#define BBUF (64 * APITCH)
#define NST 4
#define GEMM32_SMEM ((NST * (ABUF + BBUF)) * sizeof(float))

__global__ __launch_bounds__(256)
void mma_gemm_in_kernel(const float* __restrict__ A,
                        const float* __restrict__ Bt,
                        const float* __restrict__ bias) {
    constexpr int KDIM = Ff, NC = KDIM / 32;
    extern __shared__ float sh[];
    float* AsBase = sh;
    float* BsBase = sh + NST * ABUF;

    const int t = threadIdx.x;
    const int wid = t >> 5, lane = t & 31;
    const int gid = lane >> 2, tig = lane & 3;
    const int wy = wid >> 1, wx = wid & 1;
    const int col0 = blockIdx.x * 64;
    const int row0 = blockIdx.y * 128;
    const int g = blockIdx.z;

    const float* Ag = A + ((long)g * Nn + row0) * KDIM;
    float* Cg = g_X0 + ((long)g * Nn + row0) * Hh;
    uint32_t* Cb = g_X0b + ((long)g * Nn + row0) * (Hh / 2);

    #define ISSUE32(c, s) do { \
        _Pragma("unroll") \
        for (int i = 0; i < 4; i++) { \
            int f = t + i * 256; \
            int row = f >> 3, c4 = f & 7; \
            cp16(&AsBase[(s) * ABUF + row * APITCH + c4 * 4], \
                 &Ag[(long)row * KDIM + (c) * 32 + c4 * 4]); \
        } \
        _Pragma("unroll") \
        for (int i = 0; i < 2; i++) { \
            int f = t + i * 256; \
            int n = f >> 3, c4 = f & 7; \
            cp16(&BsBase[(s) * BBUF + n * APITCH + c4 * 4], \
                 &Bt[(long)(col0 + n) * KDIM + (c) * 32 + c4 * 4]); \
        } \
        CP_COMMIT(); \
    } while (0)

    float acc[2][4][4] = {};
    ISSUE32(0, 0);
    ISSUE32(1, 1);
    ISSUE32(2, 2);

    for (int c = 0; c < NC; c++) {
        int rem = NC - 1 - c;
        if (rem >= 2) CP_WAIT2(); else if (rem == 1) CP_WAIT1(); else CP_WAIT0();
        __syncthreads();
        if (c + 3 < NC) ISSUE32(c + 3, (c + 3) % NST);

        const float* As = AsBase + (c % NST) * ABUF;
        const float* Bs = BsBase + (c % NST) * BBUF;

        #pragma unroll
        for (int ks = 0; ks < 4; ks++) {
            const int kk = ks * 8 + tig;
            uint32_t a[2][4];
            #pragma unroll
            for (int mt = 0; mt < 2; mt++) {
                int mr = wy * 32 + mt * 16 + gid;
                a[mt][0] = frag_tf32(As[(mr    ) * APITCH + kk]);
                a[mt][1] = frag_tf32(As[(mr + 8) * APITCH + kk]);
                a[mt][2] = frag_tf32(As[(mr    ) * APITCH + kk + 4]);
                a[mt][3] = frag_tf32(As[(mr + 8) * APITCH + kk + 4]);
            }
            uint32_t b[4][2];
            #pragma unroll
            for (int nt = 0; nt < 4; nt++) {
                int nr = wx * 32 + nt * 8 + gid;
                b[nt][0] = __float_as_uint(Bs[nr * APITCH + kk]);
                b[nt][1] = __float_as_uint(Bs[nr * APITCH + kk + 4]);
            }
            #pragma unroll
            for (int mt = 0; mt < 2; mt++)
                #pragma unroll
                for (int nt = 0; nt < 4; nt++)
                    mma_tf32(acc[mt][nt][0], acc[mt][nt][1],
                             acc[mt][nt][2], acc[mt][nt][3],
                             a[mt][0], a[mt][1], a[mt][2], a[mt][3],
                             b[nt][0], b[nt][1]);
        }
    }

    #pragma unroll
    for (int mt = 0; mt < 2; mt++) {
        int r = wy * 32 + mt * 16 + gid;
        #pragma unroll
        for (int nt = 0; nt < 4; nt++) {
            int cc = col0 + wx * 32 + nt * 8 + 2 * tig;
            float b0 = bias[cc], b1 = bias[cc + 1];
            float v0 = fmaxf(acc[mt][nt][0] + b0, 0.f);
            float v1 = fmaxf(acc[mt][nt][1] + b1, 0.f);
            float v2 = fmaxf(acc[mt][nt][2] + b0, 0.f);
            float v3 = fmaxf(acc[mt][nt][3] + b1, 0.f);
            *reinterpret_cast<float2*>(&Cg[(long)r * Hh + cc]) = make_float2(v0, v1);
            *reinterpret_cast<float2*>(&Cg[(long)(r + 8) * Hh + cc]) = make_float2(v2, v3);
            __nv_bfloat162 p0 = __float22bfloat162_rn(make_float2(v0, v1));
            __nv_bfloat162 p1 = __float22bfloat162_rn(make_float2(v2, v3));
            Cb[(long)r * (Hh / 2) + cc / 2]       = *reinterpret_cast<uint32_t*>(&p0);
            Cb[(long)(r + 8) * (Hh / 2) + cc / 2] = *reinterpret_cast<uint32_t*>(&p1);
        }
    }
}

// ---------------- bf16 layer GEMM: Yb = Xb @ Wtb^T, 4-stage -------------------
#define WPITCH 20
#define ABUFW (128 * WPITCH)
#define BBUFW (64 * WPITCH)
#define GEMM16_SMEM ((NST * (ABUFW + BBUFW)) * sizeof(uint32_t))

__global__ __launch_bounds__(256)
void mma_gemm_bf16_kernel(const uint32_t* __restrict__ A,   // bf16x2 words
                          const uint32_t* __restrict__ Bt,  // bf16x2 words
                          uint32_t* __restrict__ Yout) {
    constexpr int NC = Hh / 32;      // 8 chunks of 32 bf16
    constexpr int KW = Hh / 2;       // 128 words per row
    extern __shared__ uint32_t shw[];
    uint32_t* AsBase = shw;
    uint32_t* BsBase = shw + NST * ABUFW;

    const int t = threadIdx.x;
    const int wid = t >> 5, lane = t & 31;
    const int gid = lane >> 2, tig = lane & 3;
    const int wy = wid >> 1, wx = wid & 1;
    const int col0 = blockIdx.x * 64;
    const int row0 = blockIdx.y * 128;
    const int g = blockIdx.z;

    const uint32_t* Ag = A + ((long)g * Nn + row0) * KW;
    uint32_t* Yb = Yout + ((long)g * Nn + row0) * (Hh / 2);

    #define ISSUE16(c, s) do { \
        _Pragma("unroll") \
        for (int i = 0; i < 2; i++) { \
            int f = t + i * 256; \
            int row = f >> 2, c4 = f & 3; \
            cp16(&AsBase[(s) * ABUFW + row * WPITCH + c4 * 4], \
                 &Ag[(long)row * KW + (c) * 16 + c4 * 4]); \
        } \
        { \
            int row = t >> 2, c4 = t & 3; \
            cp16(&BsBase[(s) * BBUFW + row * WPITCH + c4 * 4], \
                 &Bt[(long)(col0 + row) * KW + (c) * 16 + c4 * 4]); \
        } \
        CP_COMMIT(); \
    } while (0)

    float acc[2][4][4] = {};
    ISSUE16(0, 0);
    ISSUE16(1, 1);
    ISSUE16(2, 2);

    for (int c = 0; c < NC; c++) {
        int rem = NC - 1 - c;
        if (rem >= 2) CP_WAIT2(); else if (rem == 1) CP_WAIT1(); else CP_WAIT0();
        __syncthreads();
        if (c + 3 < NC) ISSUE16(c + 3, (c + 3) % NST);

        const uint32_t* As = AsBase + (c % NST) * ABUFW;
        const uint32_t* Bs = BsBase + (c % NST) * BBUFW;

        #pragma unroll
        for (int ks = 0; ks < 2; ks++) {
            const int kw = ks * 8 + tig;
            uint32_t a[2][4];
            #pragma unroll
            for (int mt = 0; mt < 2; mt++) {
                int mr = wy * 32 + mt * 16 + gid;
                a[mt][0] = As[(mr    ) * WPITCH + kw];
                a[mt][1] = As[(mr + 8) * WPITCH + kw];
                a[mt][2] = As[(mr    ) * WPITCH + kw + 4];
                a[mt][3] = As[(mr + 8) * WPITCH + kw + 4];
            }
            uint32_t b[4][2];
            #pragma unroll
            for (int nt = 0; nt < 4; nt++) {
                int nr = wx * 32 + nt * 8 + gid;
                b[nt][0] = Bs[nr * WPITCH + kw];
                b[nt][1] = Bs[nr * WPITCH + kw + 4];
            }
            #pragma unroll
            for (int mt = 0; mt < 2; mt++)
                #pragma unroll
                for (int nt = 0; nt < 4; nt++)
                    mma_bf16(acc[mt][nt][0], acc[mt][nt][1],
                             acc[mt][nt][2], acc[mt][nt][3],
                             a[mt][0], a[mt][1], a[mt][2], a[mt][3],
                             b[nt][0], b[nt][1]);
        }
    }

    #pragma unroll
    for (int mt = 0; mt < 2; mt++) {
        int r = wy * 32 + mt * 16 + gid;
        #pragma unroll
        for (int nt = 0; nt < 4; nt++) {
            int cc = col0 + wx * 32 + nt * 8 + 2 * tig;
            __nv_bfloat162 p0 = __float22bfloat162_rn(
                make_float2(acc[mt][nt][0], acc[mt][nt][1]));
            __nv_bfloat162 p1 = __float22bfloat162_rn(
                make_float2(acc[mt][nt][2], acc[mt][nt][3]));
            Yb[(long)r * (Hh / 2) + cc / 2]       = *reinterpret_cast<uint32_t*>(&p0);
            Yb[(long)(r + 8) * (Hh / 2) + cc / 2] = *reinterpret_cast<uint32_t*>(&p1);
        }
    }
}

// ---------------- SpMM relu: 2 rows per 256-thread block ---------------------
__global__ __launch_bounds__(256)
void spmm_relu_kernel(const float* __restrict__ bias) {
    int g = blockIdx.y;
    int n = blockIdx.x * 2 + (threadIdx.x >> 7);   // row per 128-thread half
    int t = threadIdx.x & 127;
    int half = threadIdx.x >> 7;
    long rbase = (long)g * Nn + n;
    int nnz = g_nnz[rbase];

    __shared__ unsigned short scol[2][CAP];
    __shared__ float sval[2][CAP];
    for (int j = t; j < nnz; j += 128) {
        scol[half][j] = g_cols[rbase * CAP + j];
        sval[half][j] = g_vals[rbase * CAP + j];
    }
    __syncthreads();

    const uint32_t* Yg = g_Yb + (long)g * Nn * (Hh / 2);
    float a0 = 0.f, a1 = 0.f;
    int j = 0;
    for (; j + 8 <= nnz; j += 8) {
        uint32_t w[8];
        #pragma unroll
        for (int q = 0; q < 8; q++)
            w[q] = Yg[(long)scol[half][j + q] * (Hh / 2) + t];
        #pragma unroll
        for (int q = 0; q < 8; q++) {
            float2 f = __bfloat1622float2(*reinterpret_cast<__nv_bfloat162*>(&w[q]));
            a0 += sval[half][j + q] * f.x;
            a1 += sval[half][j + q] * f.y;
        }
    }
    if (j + 4 <= nnz) {
        uint32_t w[4];
        #pragma unroll
        for (int q = 0; q < 4; q++)
            w[q] = Yg[(long)scol[half][j + q] * (Hh / 2) + t];
        #pragma unroll
        for (int q = 0; q < 4; q++) {
            float2 f = __bfloat1622float2(*reinterpret_cast<__nv_bfloat162*>(&w[q]));
            a0 += sval[half][j + q] * f.x;
            a1 += sval[half][j + q] * f.y;
        }
        j += 4;
    }
    for (; j < nnz; j++) {
        uint32_t w = Yg[(long)scol[half][j] * (Hh / 2) + t];
        float2 f = __bfloat1622float2(*reinterpret_cast<__nv_bfloat162*>(&w));
        a0 += sval[half][j] * f.x;
        a1 += sval[half][j] * f.y;
    }

    float2 bv = *reinterpret_cast<const float2*>(&bias[2 * t]);
    __nv_bfloat162 p = __float22bfloat162_rn(
        make_float2(fmaxf(a0 + bv.x, 0.f), fmaxf(a1 + bv.y, 0.f)));
    g_Xb[rbase * (Hh / 2) + t] = *reinterpret_cast<uint32_t*>(&p);
}

// ---------------- SpMM last: softmax + residual, 1 row / 128 thr -------------
__global__ __launch_bounds__(128)
void spmm_last_kernel(const float* __restrict__ bias) {
    int g = blockIdx.y;
    int n = blockIdx.x;
    int t = threadIdx.x;
    int lane = t & 31, wid = t >> 5;
    long rbase = (long)g * Nn + n;
    int nnz = g_nnz[rbase];

    __shared__ unsigned short scol[CAP];
    __shared__ float sval[CAP];
    for (int j = t; j < nnz; j += 128) {
        scol[j] = g_cols[rbase * CAP + j];
        sval[j] = g_vals[rbase * CAP + j];
    }
    __syncthreads();

    const uint32_t* Yg = g_Yb + (long)g * Nn * (Hh / 2);
    float a0 = 0.f, a1 = 0.f;
    int j = 0;
    for (; j + 8 <= nnz; j += 8) {
        uint32_t w[8];
        #pragma unroll
        for (int q = 0; q < 8; q++)
            w[q] = Yg[(long)scol[j + q] * (Hh / 2) + t];
        #pragma unroll
        for (int q = 0; q < 8; q++) {
            float2 f = __bfloat1622float2(*reinterpret_cast<__nv_bfloat162*>(&w[q]));
            a0 += sval[j + q] * f.x;
            a1 += sval[j + q] * f.y;
        }
    }
    for (; j < nnz; j++) {
        uint32_t w = Yg[(long)scol[j] * (Hh / 2) + t];
        float2 f = __bfloat1622float2(*reinterpret_cast<__nv_bfloat162*>(&w));
        a0 += sval[j] * f.x;
        a1 += sval[j] * f.y;
    }

    float2 bv = *reinterpret_cast<const float2*>(&bias[2 * t]);
    float v0 = a0 + bv.x, v1 = a1 + bv.y;

    __shared__ float smax[4], ssum[4];
    float m = fmaxf(v0, v1);
    #pragma unroll
    for (int off = 16; off > 0; off >>= 1)
        m = fmaxf(m, __shfl_xor_sync(0xFFFFFFFFu, m, off));
    if (lane == 0) smax[wid] = m;
    __syncthreads();
    m = fmaxf(fmaxf(smax[0], smax[1]), fmaxf(smax[2], smax[3]));
    float e0 = expf(v0 - m), e1 = expf(v1 - m);
    float s = e0 + e1;
    #pragma unroll
    for (int off = 16; off > 0; off >>= 1)
        s += __shfl_xor_sync(0xFFFFFFFFu, s, off);
    if (lane == 0) ssum[wid] = s;
    __syncthreads();
    s = (ssum[0] + ssum[1]) + (ssum[2] + ssum[3]);
    float inv = 1.0f / s;
    float2 x0 = reinterpret_cast<const float2*>(g_X0)[rbase * (Hh / 2) + t];
    reinterpret_cast<float2*>(g_X)[rbase * (Hh / 2) + t] =
        make_float2(e0 * inv + x0.x, e1 * inv + x0.y);
}

// ---------------- per-sample masked mean -------------------------------------
__global__ void masked_mean_kernel(const int* __restrict__ graph,
                                   float* __restrict__ out) {
    int b = blockIdx.x;
    int chunk = blockIdx.y;
    int h = threadIdx.x;
    int g = graph[b];
    const float* xg = g_X + ((long)g * Nn + chunk * 128) * Hh;
    const float* mb = g_maskf + (long)b * Nn + chunk * 128;
    float acc = 0.f;
    #pragma unroll 4
    for (int n = 0; n < 128; n++) {
        float mv = mb[n];
        if (mv != 0.f) acc += xg[(long)n * Hh + h];
    }
    atomicAdd(&out[(long)b * Hh + h], acc / g_cnt[b]);
}

// ---------------- launch -----------------------------------------------------
extern "C" void kernel_launch(void* const* d_in, const int* in_sizes, int n_in,
                              void* d_out, int out_size) {
    const int*   graph = (const int*)  d_in[0];
    const void*  mask  =               d_in[1];
    const float* xs    = (const float*)d_in[2];
    const float* Adj   = (const float*)d_in[3];
    const float* W_in  = (const float*)d_in[4];
    const float* b_in  = (const float*)d_in[5];
    const float* Ws    = (const float*)d_in[6];
    const float* bs    = (const float*)d_in[7];
    float* out = (float*)d_out;

    float *pWtIn;
    uint32_t *pX0b, *pXb, *pYb, *pWtb;
    cudaGetSymbolAddress((void**)&pWtIn, g_WtIn);
    cudaGetSymbolAddress((void**)&pX0b,  g_X0b);
    cudaGetSymbolAddress((void**)&pXb,   g_Xb);
    cudaGetSymbolAddress((void**)&pYb,   g_Yb);
    cudaGetSymbolAddress((void**)&pWtb,  g_Wtb);

    cudaFuncSetAttribute(mma_gemm_in_kernel,
        cudaFuncAttributeMaxDynamicSharedMemorySize, (int)GEMM32_SMEM);
    cudaFuncSetAttribute(mma_gemm_bf16_kernel,
        cudaFuncAttributeMaxDynamicSharedMemorySize, (int)GEMM16_SMEM);

    // merged CSR + mask + zero + transposes (one launch)
    csr_mask_prep_kernel<<<PREP_BLKS, 256>>>(Adj, mask, out, Ws, W_in);

    dim3 ggrid(Hh / 64, Nn / 128, Gg);   // 256 CTAs

    // X0 = relu(xs @ W_in + b_in)  [tf32; fp32 + bf16 copies]
    mma_gemm_in_kernel<<<ggrid, 256, GEMM32_SMEM>>>(xs, pWtIn, b_in);

    dim3 sp_relu_grid(Nn / 2, Gg);
    dim3 sp_last_grid(Nn, Gg);
    const uint32_t* xin = pX0b;
    for (int i = 0; i < Ll; i++) {
        mma_gemm_bf16_kernel<<<ggrid, 256, GEMM16_SMEM>>>(
            xin, pWtb + (long)i * Hh * Hh / 2, pYb);
        if (i < Ll - 1)
            spmm_relu_kernel<<<sp_relu_grid, 256>>>(bs + (long)i * Hh);
        else
            spmm_last_kernel<<<sp_last_grid, 128>>>(bs + (long)i * Hh);
        xin = pXb;
    }

    dim3 mm_grid(Bb, Nn / 128);
    masked_mean_kernel<<<mm_grid, Hh>>>(graph, out);
}

// round 11
// speedup vs baseline: 1.3842x; 1.3842x over previous
#include <cuda_runtime.h>
#include <cuda_bf16.h>
#include <cstdint>

// Problem constants
#define Gg 8
#define Nn 1024
#define Ff 128
#define Hh 256
#define Ll 4
#define Bb 64
#define CAP 128

// ---------------- scratch (device globals) ----------------------------------
__device__ __align__(16) float    g_X0 [Gg * Nn * Hh];          // fp32 residual
__device__ __align__(16) uint32_t g_X0b[Gg * Nn * Hh / 2];      // bf16x2 copy of X0
__device__ __align__(16) float    g_X  [Gg * Nn * Hh];          // fp32 final x
__device__ __align__(16) uint32_t g_Xb [Gg * Nn * Hh / 2];      // bf16x2 inter-layer x
__device__ __align__(16) uint32_t g_Yb [Gg * Nn * Hh / 2];      // bf16x2 Y = x @ W
__device__ __align__(16) uint32_t g_Wtb[Ll * Hh * Hh / 2];      // bf16x2 Ws^T [l][n][k]
__device__ __align__(16) float    g_WtIn[Hh * Ff];              // W_in^T (tf32-rounded)
__device__ __align__(16) int      g_coff[(long)Gg * Nn * CAP];  // precomputed col*(Hh/2)
__device__ __align__(16) float    g_vals[(long)Gg * Nn * CAP];
__device__ int   g_nnz[Gg * Nn];
__device__ float g_maskf[Bb * Nn];
__device__ float g_cnt[Bb];
__device__ int   g_mask_mode;

// ---------------- helpers ----------------------------------------------------
__device__ __forceinline__ float f2tf32(float x) {
    uint32_t r;
    asm("cvt.rna.tf32.f32 %0, %1;" : "=r"(r) : "f"(x));
    return __uint_as_float(r);
}
__device__ __forceinline__ uint32_t frag_tf32(float x) {
    uint32_t r;
    asm("cvt.rna.tf32.f32 %0, %1;" : "=r"(r) : "f"(x));
    return r;
}

__device__ __forceinline__ void mma_tf32(float& c0, float& c1, float& c2, float& c3,
                                         uint32_t a0, uint32_t a1, uint32_t a2, uint32_t a3,
                                         uint32_t b0, uint32_t b1) {
    asm volatile(
        "mma.sync.aligned.m16n8k8.row.col.f32.tf32.tf32.f32 "
        "{%0,%1,%2,%3}, {%4,%5,%6,%7}, {%8,%9}, {%0,%1,%2,%3};"
        : "+f"(c0), "+f"(c1), "+f"(c2), "+f"(c3)
        : "r"(a0), "r"(a1), "r"(a2), "r"(a3), "r"(b0), "r"(b1));
}
__device__ __forceinline__ void mma_bf16(float& c0, float& c1, float& c2, float& c3,
                                         uint32_t a0, uint32_t a1, uint32_t a2, uint32_t a3,
                                         uint32_t b0, uint32_t b1) {
    asm volatile(
        "mma.sync.aligned.m16n8k16.row.col.f32.bf16.bf16.f32 "
        "{%0,%1,%2,%3}, {%4,%5,%6,%7}, {%8,%9}, {%0,%1,%2,%3};"
        : "+f"(c0), "+f"(c1), "+f"(c2), "+f"(c3)
        : "r"(a0), "r"(a1), "r"(a2), "r"(a3), "r"(b0), "r"(b1));
}

__device__ __forceinline__ void cp16(void* dst_smem, const void* src) {
    uint32_t d = (uint32_t)__cvta_generic_to_shared(dst_smem);
    asm volatile("cp.async.cg.shared.global [%0], [%1], 16;"
                 :: "r"(d), "l"(src) : "memory");
}
#define CP_COMMIT() asm volatile("cp.async.commit_group;" ::: "memory")
#define CP_WAIT1()  asm volatile("cp.async.wait_group 1;" ::: "memory")
#define CP_WAIT0()  asm volatile("cp.async.wait_group 0;" ::: "memory")

// ---------------- prep: zero d_out + detect mask + weight transposes ---------
__global__ void prep_kernel(const unsigned int* __restrict__ m,
                            float* __restrict__ out,
                            const float* __restrict__ Ws,
                            const float* __restrict__ W_in) {
    const int t = threadIdx.y * 32 + threadIdx.x;
    const int bid = blockIdx.x;

    if (bid < Bb) {
        out[(long)bid * 256 + t] = 0.0f;
        if (bid != 0) return;
        __shared__ int sh_f, sh_b;
        if (t == 0) { sh_f = 0; sh_b = 0; }
        __syncthreads();
        int f = 0, b = 0;
        for (int i = t; i < 16384; i += 256) {
            unsigned int w = m[i];
            if (w == 0x3F800000u) f = 1;
            if (w > 1u && (w & ~0x01010101u) == 0u) b = 1;
        }
        if (f) atomicOr(&sh_f, 1);
        if (b) atomicOr(&sh_b, 1);
        __syncthreads();
        if (t == 0) g_mask_mode = sh_f ? 1 : (sh_b ? 2 : 0);
        return;
    }

    __shared__ float tile[32][33];
    int idx = bid - Bb;
    int z = idx >> 6;           // 0..4
    int rem = idx & 63;
    int bx = rem & 7, by = rem >> 3;
    int x = threadIdx.x, y = threadIdx.y;

    if (z < Ll) {
        const float* src = Ws + (long)z * Hh * Hh;
        __nv_bfloat16* dst = reinterpret_cast<__nv_bfloat16*>(g_Wtb) + (long)z * Hh * Hh;
        int k0 = bx * 32, h0 = by * 32;
        #pragma unroll
        for (int j = 0; j < 32; j += 8)
            tile[y + j][x] = src[(long)(k0 + y + j) * Hh + h0 + x];
        __syncthreads();
        #pragma unroll
        for (int j = 0; j < 32; j += 8)
            dst[(long)(h0 + y + j) * Hh + k0 + x] = __float2bfloat16(tile[x][y + j]);
    } else {
        if (bx >= Ff / 32) return;
        int k0 = bx * 32, h0 = by * 32;
        #pragma unroll
        for (int j = 0; j < 32; j += 8)
            tile[y + j][x] = W_in[(long)(k0 + y + j) * Hh + h0 + x];
        __syncthreads();
        #pragma unroll
        for (int j = 0; j < 32; j += 8)
            g_WtIn[(long)(h0 + y + j) * Ff + k0 + x] = f2tf32(tile[x][y + j]);
    }
}

// ---------------- CSR build + mask expand (merged) ---------------------------
// CSR stores precomputed word offsets (col * Hh/2) so SpMM does no multiply.
__global__ void csr_mask_kernel(const float* __restrict__ Adj,
                                const void* __restrict__ mraw) {
    __shared__ int cnt;
    if (blockIdx.y < Gg) {
        int g = blockIdx.y;
        int n = blockIdx.x;
        long rbase = (long)g * Nn + n;
        const float* row = Adj + rbase * Nn;
        if (threadIdx.x == 0) cnt = 0;
        __syncthreads();
        for (int m = threadIdx.x; m < Nn; m += blockDim.x) {
            float v = row[m];
            if (v != 0.0f) {
                int p = atomicAdd(&cnt, 1);
                if (p < CAP) {
                    g_coff[rbase * CAP + p] = m * (Hh / 2);
                    g_vals[rbase * CAP + p] = v;
                }
            }
        }
        __syncthreads();
        if (threadIdx.x == 0) g_nnz[rbase] = cnt < CAP ? cnt : CAP;
    } else {
        int b = blockIdx.x;
        if (b >= Bb) return;
        int mode = g_mask_mode;
        if (threadIdx.x == 0) cnt = 0;
        __syncthreads();
        int local = 0;
        for (int n = threadIdx.x; n < Nn; n += blockDim.x) {
            long idx = (long)b * Nn + n;
            bool on;
            if (mode == 1)      on = ((const float*)mraw)[idx] != 0.0f;
            else if (mode == 2) on = ((const unsigned char*)mraw)[idx] != 0;
            else                on = ((const int*)mraw)[idx] != 0;
            g_maskf[idx] = on ? 1.0f : 0.0f;
            local += on ? 1 : 0;
        }
        atomicAdd(&cnt, local);
        __syncthreads();
        if (threadIdx.x == 0) g_cnt[b] = (float)(cnt < 1 ? 1 : cnt);
    }
}

// ---------------- tf32 input GEMM (fp32 A), 3-stage single-sync, 128x64 ------
#define APITCH 36
#define ABUF (128 * APITCH)
#define BBUF (64 * APITCH)
#define NSTAGE 3
#define GEMM32_SMEM ((NSTAGE * (ABUF + BBUF)) * sizeof(float))

__global__ __launch_bounds__(256)
void mma_gemm_in_kernel(const float* __restrict__ A,
                        const float* __restrict__ Bt,
                        const float* __restrict__ bias) {
    constexpr int KDIM = Ff, NC = KDIM / 32;
    extern __shared__ float sh[];
    float* AsBase = sh;
    float* BsBase = sh + NSTAGE * ABUF;

    const int t = threadIdx.x;
    const int wid = t >> 5, lane = t & 31;
    const int gid = lane >> 2, tig = lane & 3;
    const int wy = wid >> 1, wx = wid & 1;
    const int col0 = blockIdx.x * 64;
    const int row0 = blockIdx.y * 128;
    const int g = blockIdx.z;

    const float* Ag = A + ((long)g * Nn + row0) * KDIM;
    float* Cg = g_X0 + ((long)g * Nn + row0) * Hh;
    uint32_t* Cb = g_X0b + ((long)g * Nn + row0) * (Hh / 2);

    #define ISSUE32(c, s) do { \
        _Pragma("unroll") \
        for (int i = 0; i < 4; i++) { \
            int f = t + i * 256; \
            int row = f >> 3, c4 = f & 7; \
            cp16(&AsBase[(s) * ABUF + row * APITCH + c4 * 4], \
                 &Ag[(long)row * KDIM + (c) * 32 + c4 * 4]); \
        } \
        _Pragma("unroll") \
        for (int i = 0; i < 2; i++) { \
            int f = t + i * 256; \
            int n = f >> 3, c4 = f & 7; \
            cp16(&BsBase[(s) * BBUF + n * APITCH + c4 * 4], \
                 &Bt[(long)(col0 + n) * KDIM + (c) * 32 + c4 * 4]); \
        } \
        CP_COMMIT(); \
    } while (0)

    float acc[2][4][4] = {};
    ISSUE32(0, 0);
    ISSUE32(1, 1);

    for (int c = 0; c < NC; c++) {
        if (c + 1 < NC) CP_WAIT1(); else CP_WAIT0();
        __syncthreads();
        if (c + 2 < NC) ISSUE32(c + 2, (c + 2) % NSTAGE);

        const float* As = AsBase + (c % NSTAGE) * ABUF;
        const float* Bs = BsBase + (c % NSTAGE) * BBUF;

        #pragma unroll
        for (int ks = 0; ks < 4; ks++) {
            const int kk = ks * 8 + tig;
            uint32_t a[2][4];
            #pragma unroll
            for (int mt = 0; mt < 2; mt++) {
                int mr = wy * 32 + mt * 16 + gid;
                a[mt][0] = frag_tf32(As[(mr    ) * APITCH + kk]);
                a[mt][1] = frag_tf32(As[(mr + 8) * APITCH + kk]);
                a[mt][2] = frag_tf32(As[(mr    ) * APITCH + kk + 4]);
                a[mt][3] = frag_tf32(As[(mr + 8) * APITCH + kk + 4]);
            }
            uint32_t b[4][2];
            #pragma unroll
            for (int nt = 0; nt < 4; nt++) {
                int nr = wx * 32 + nt * 8 + gid;
                b[nt][0] = __float_as_uint(Bs[nr * APITCH + kk]);
                b[nt][1] = __float_as_uint(Bs[nr * APITCH + kk + 4]);
            }
            #pragma unroll
            for (int mt = 0; mt < 2; mt++)
                #pragma unroll
                for (int nt = 0; nt < 4; nt++)
                    mma_tf32(acc[mt][nt][0], acc[mt][nt][1],
                             acc[mt][nt][2], acc[mt][nt][3],
                             a[mt][0], a[mt][1], a[mt][2], a[mt][3],
                             b[nt][0], b[nt][1]);
        }
    }

    #pragma unroll
    for (int mt = 0; mt < 2; mt++) {
        int r = wy * 32 + mt * 16 + gid;
        #pragma unroll
        for (int nt = 0; nt < 4; nt++) {
            int cc = col0 + wx * 32 + nt * 8 + 2 * tig;
            float b0 = bias[cc], b1 = bias[cc + 1];
            float v0 = fmaxf(acc[mt][nt][0] + b0, 0.f);
            float v1 = fmaxf(acc[mt][nt][1] + b1, 0.f);
            float v2 = fmaxf(acc[mt][nt][2] + b0, 0.f);
            float v3 = fmaxf(acc[mt][nt][3] + b1, 0.f);
            *reinterpret_cast<float2*>(&Cg[(long)r * Hh + cc]) = make_float2(v0, v1);
            *reinterpret_cast<float2*>(&Cg[(long)(r + 8) * Hh + cc]) = make_float2(v2, v3);
            __nv_bfloat162 p0 = __float22bfloat162_rn(make_float2(v0, v1));
            __nv_bfloat162 p1 = __float22bfloat162_rn(make_float2(v2, v3));
            Cb[(long)r * (Hh / 2) + cc / 2]       = *reinterpret_cast<uint32_t*>(&p0);
            Cb[(long)(r + 8) * (Hh / 2) + cc / 2] = *reinterpret_cast<uint32_t*>(&p1);
        }
    }
}

// ---------------- bf16 layer GEMM: Yb = Xb @ Wtb^T, 3-stage -------------------
#define WPITCH 20
#define ABUFW (128 * WPITCH)
#define BBUFW (64 * WPITCH)
#define GEMM16_SMEM ((NSTAGE * (ABUFW + BBUFW)) * sizeof(uint32_t))

__global__ __launch_bounds__(256)
void mma_gemm_bf16_kernel(const uint32_t* __restrict__ A,   // bf16x2 words
                          const uint32_t* __restrict__ Bt,  // bf16x2 words
                          uint32_t* __restrict__ Yout) {
    constexpr int NC = Hh / 32;      // 8 chunks of 32 bf16
    constexpr int KW = Hh / 2;       // 128 words per row
    extern __shared__ uint32_t shw[];
    uint32_t* AsBase = shw;
    uint32_t* BsBase = shw + NSTAGE * ABUFW;

    const int t = threadIdx.x;
    const int wid = t >> 5, lane = t & 31;
    const int gid = lane >> 2, tig = lane & 3;
    const int wy = wid >> 1, wx = wid & 1;
    const int col0 = blockIdx.x * 64;
    const int row0 = blockIdx.y * 128;
    const int g = blockIdx.z;

    const uint32_t* Ag = A + ((long)g * Nn + row0) * KW;
    uint32_t* Yb = Yout + ((long)g * Nn + row0) * (Hh / 2);

    #define ISSUE16(c, s) do { \
        _Pragma("unroll") \
        for (int i = 0; i < 2; i++) { \
            int f = t + i * 256; \
            int row = f >> 2, c4 = f & 3; \
            cp16(&AsBase[(s) * ABUFW + row * WPITCH + c4 * 4], \
                 &Ag[(long)row * KW + (c) * 16 + c4 * 4]); \
        } \
        { \
            int row = t >> 2, c4 = t & 3; \
            cp16(&BsBase[(s) * BBUFW + row * WPITCH + c4 * 4], \
                 &Bt[(long)(col0 + row) * KW + (c) * 16 + c4 * 4]); \
        } \
        CP_COMMIT(); \
    } while (0)

    float acc[2][4][4] = {};
    ISSUE16(0, 0);
    ISSUE16(1, 1);

    for (int c = 0; c < NC; c++) {
        if (c + 1 < NC) CP_WAIT1(); else CP_WAIT0();
        __syncthreads();
        if (c + 2 < NC) ISSUE16(c + 2, (c + 2) % NSTAGE);

        const uint32_t* As = AsBase + (c % NSTAGE) * ABUFW;
        const uint32_t* Bs = BsBase + (c % NSTAGE) * BBUFW;

        #pragma unroll
        for (int ks = 0; ks < 2; ks++) {
            const int kw = ks * 8 + tig;
            uint32_t a[2][4];
            #pragma unroll
            for (int mt = 0; mt < 2; mt++) {
                int mr = wy * 32 + mt * 16 + gid;
                a[mt][0] = As[(mr    ) * WPITCH + kw];
                a[mt][1] = As[(mr + 8) * WPITCH + kw];
                a[mt][2] = As[(mr    ) * WPITCH + kw + 4];
                a[mt][3] = As[(mr + 8) * WPITCH + kw + 4];
            }
            uint32_t b[4][2];
            #pragma unroll
            for (int nt = 0; nt < 4; nt++) {
                int nr = wx * 32 + nt * 8 + gid;
                b[nt][0] = Bs[nr * WPITCH + kw];
                b[nt][1] = Bs[nr * WPITCH + kw + 4];
            }
            #pragma unroll
            for (int mt = 0; mt < 2; mt++)
                #pragma unroll
                for (int nt = 0; nt < 4; nt++)
                    mma_bf16(acc[mt][nt][0], acc[mt][nt][1],
                             acc[mt][nt][2], acc[mt][nt][3],
                             a[mt][0], a[mt][1], a[mt][2], a[mt][3],
                             b[nt][0], b[nt][1]);
        }
    }

    #pragma unroll
    for (int mt = 0; mt < 2; mt++) {
        int r = wy * 32 + mt * 16 + gid;
        #pragma unroll
        for (int nt = 0; nt < 4; nt++) {
            int cc = col0 + wx * 32 + nt * 8 + 2 * tig;
            __nv_bfloat162 p0 = __float22bfloat162_rn(
                make_float2(acc[mt][nt][0], acc[mt][nt][1]));
            __nv_bfloat162 p1 = __float22bfloat162_rn(
                make_float2(acc[mt][nt][2], acc[mt][nt][3]));
            Yb[(long)r * (Hh / 2) + cc / 2]       = *reinterpret_cast<uint32_t*>(&p0);
            Yb[(long)(r + 8) * (Hh / 2) + cc / 2] = *reinterpret_cast<uint32_t*>(&p1);
        }
    }
}

// ---------------- SpMM: X = act(A_sparse @ Yb + bias) ------------------------
// 128 threads, 1 row; CSR carries precomputed word offsets -> no mul in loop.
template<bool LAST>
__global__ __launch_bounds__(128)
void spmm_kernel(const float* __restrict__ bias) {
    int g = blockIdx.y;
    int n = blockIdx.x;
    int t = threadIdx.x;
    int lane = t & 31, wid = t >> 5;
    long rbase = (long)g * Nn + n;
    int nnz = g_nnz[rbase];

    __shared__ int   soff[CAP];
    __shared__ float sval[CAP];
    for (int j = t; j < nnz; j += 128) {
        soff[j] = g_coff[rbase * CAP + j];
        sval[j] = g_vals[rbase * CAP + j];
    }
    __syncthreads();

    const uint32_t* Yt = g_Yb + (long)g * Nn * (Hh / 2) + t;   // hoist +t
    float a0 = 0.f, a1 = 0.f;
    int j = 0;
    for (; j + 8 <= nnz; j += 8) {
        uint32_t w[8];
        #pragma unroll
        for (int q = 0; q < 8; q++)
            w[q] = Yt[soff[j + q]];
        #pragma unroll
        for (int q = 0; q < 8; q++) {
            float2 f = __bfloat1622float2(*reinterpret_cast<__nv_bfloat162*>(&w[q]));
            a0 += sval[j + q] * f.x;
            a1 += sval[j + q] * f.y;
        }
    }
    if (j + 4 <= nnz) {
        uint32_t w[4];
        #pragma unroll
        for (int q = 0; q < 4; q++)
            w[q] = Yt[soff[j + q]];
        #pragma unroll
        for (int q = 0; q < 4; q++) {
            float2 f = __bfloat1622float2(*reinterpret_cast<__nv_bfloat162*>(&w[q]));
            a0 += sval[j + q] * f.x;
            a1 += sval[j + q] * f.y;
        }
        j += 4;
    }
    for (; j < nnz; j++) {
        uint32_t w = Yt[soff[j]];
        float2 f = __bfloat1622float2(*reinterpret_cast<__nv_bfloat162*>(&w));
        a0 += sval[j] * f.x;
        a1 += sval[j] * f.y;
    }

    float2 bv = *reinterpret_cast<const float2*>(&bias[2 * t]);
    float v0 = a0 + bv.x, v1 = a1 + bv.y;

    if (!LAST) {
        __nv_bfloat162 p = __float22bfloat162_rn(
            make_float2(fmaxf(v0, 0.f), fmaxf(v1, 0.f)));
        g_Xb[rbase * (Hh / 2) + t] = *reinterpret_cast<uint32_t*>(&p);
    } else {
        __shared__ float smax[4], ssum[4];
        float m = fmaxf(v0, v1);
        #pragma unroll
        for (int off = 16; off > 0; off >>= 1)
            m = fmaxf(m, __shfl_xor_sync(0xFFFFFFFFu, m, off));
        if (lane == 0) smax[wid] = m;
        __syncthreads();
        m = fmaxf(fmaxf(smax[0], smax[1]), fmaxf(smax[2], smax[3]));
        float e0 = expf(v0 - m), e1 = expf(v1 - m);
        float s = e0 + e1;
        #pragma unroll
        for (int off = 16; off > 0; off >>= 1)
            s += __shfl_xor_sync(0xFFFFFFFFu, s, off);
        if (lane == 0) ssum[wid] = s;
        __syncthreads();
        s = (ssum[0] + ssum[1]) + (ssum[2] + ssum[3]);
        float inv = 1.0f / s;
        float2 x0 = reinterpret_cast<const float2*>(g_X0)[rbase * (Hh / 2) + t];
        reinterpret_cast<float2*>(g_X)[rbase * (Hh / 2) + t] =
            make_float2(e0 * inv + x0.x, e1 * inv + x0.y);
    }
}

// ---------------- per-sample masked mean -------------------------------------
__global__ void masked_mean_kernel(const int* __restrict__ graph,
                                   float* __restrict__ out) {
    int b = blockIdx.x;
    int chunk = blockIdx.y;
    int h = threadIdx.x;
    int g = graph[b];
    const float* xg = g_X + ((long)g * Nn + chunk * 128) * Hh;
    const float* mb = g_maskf + (long)b * Nn + chunk * 128;
    float acc = 0.f;
    #pragma unroll 4
    for (int n = 0; n < 128; n++) {
        float mv = mb[n];
        if (mv != 0.f) acc += xg[(long)n * Hh + h];
    }
    atomicAdd(&out[(long)b * Hh + h], acc / g_cnt[b]);
}

// ---------------- launch -----------------------------------------------------
extern "C" void kernel_launch(void* const* d_in, const int* in_sizes, int n_in,
                              void* d_out, int out_size) {
    const int*   graph = (const int*)  d_in[0];
    const void*  mask  =               d_in[1];
    const float* xs    = (const float*)d_in[2];
    const float* Adj   = (const float*)d_in[3];
    const float* W_in  = (const float*)d_in[4];
    const float* b_in  = (const float*)d_in[5];
    const float* Ws    = (const float*)d_in[6];
    const float* bs    = (const float*)d_in[7];
    float* out = (float*)d_out;

    float *pWtIn;
    uint32_t *pX0b, *pXb, *pYb, *pWtb;
    cudaGetSymbolAddress((void**)&pWtIn, g_WtIn);
    cudaGetSymbolAddress((void**)&pX0b,  g_X0b);
    cudaGetSymbolAddress((void**)&pXb,   g_Xb);
    cudaGetSymbolAddress((void**)&pYb,   g_Yb);
    cudaGetSymbolAddress((void**)&pWtb,  g_Wtb);

    cudaFuncSetAttribute(mma_gemm_in_kernel,
        cudaFuncAttributeMaxDynamicSharedMemorySize, (int)GEMM32_SMEM);
    cudaFuncSetAttribute(mma_gemm_bf16_kernel,
        cudaFuncAttributeMaxDynamicSharedMemorySize, (int)GEMM16_SMEM);

    // prep: zero d_out + detect mask dtype + weight transposes
    prep_kernel<<<Bb + 320, dim3(32, 8)>>>((const unsigned int*)mask, out, Ws, W_in);

    // CSR build (precomputed offsets) + mask expand
    dim3 cm_grid(Nn, Gg + 1);
    csr_mask_kernel<<<cm_grid, 256>>>(Adj, mask);

    dim3 ggrid(Hh / 64, Nn / 128, Gg);   // 256 CTAs

    // X0 = relu(xs @ W_in + b_in)  [tf32; fp32 + bf16 copies]
    mma_gemm_in_kernel<<<ggrid, 256, GEMM32_SMEM>>>(xs, pWtIn, b_in);

    dim3 sp_grid(Nn, Gg);
    const uint32_t* xin = pX0b;
    for (int i = 0; i < Ll; i++) {
        mma_gemm_bf16_kernel<<<ggrid, 256, GEMM16_SMEM>>>(
            xin, pWtb + (long)i * Hh * Hh / 2, pYb);
        if (i < Ll - 1)
            spmm_kernel<false><<<sp_grid, 128>>>(bs + (long)i * Hh);
        else
            spmm_kernel<true><<<sp_grid, 128>>>(bs + (long)i * Hh);
        xin = pXb;
    }

    dim3 mm_grid(Bb, Nn / 128);
    masked_mean_kernel<<<mm_grid, Hh>>>(graph, out);
}

// round 12
// speedup vs baseline: 1.4174x; 1.0240x over previous
#include <cuda_runtime.h>
#include <cuda_bf16.h>
#include <cstdint>

// Problem constants
#define Gg 8
#define Nn 1024
#define Ff 128
#define Hh 256
#define Ll 4
#define Bb 64
#define CAP 128

// ---------------- scratch (device globals) ----------------------------------
__device__ __align__(16) float    g_X0 [Gg * Nn * Hh];          // fp32 residual
__device__ __align__(16) uint32_t g_X0b[Gg * Nn * Hh / 2];      // bf16x2 copy of X0
__device__ __align__(16) float    g_X  [Gg * Nn * Hh];          // fp32 final x
__device__ __align__(16) uint32_t g_Xb [Gg * Nn * Hh / 2];      // bf16x2 inter-layer x
__device__ __align__(16) uint32_t g_Yb [Gg * Nn * Hh / 2];      // bf16x2 Y = x @ W
__device__ __align__(16) uint32_t g_Wtb[Ll * Hh * Hh / 2];      // bf16x2 Ws^T [l][n][k]
__device__ __align__(16) float    g_WtIn[Hh * Ff];              // W_in^T (tf32-rounded)
__device__ __align__(16) int      g_coff[(long)Gg * Nn * CAP];  // precomputed col*(Hh/2)
__device__ __align__(16) float    g_vals[(long)Gg * Nn * CAP];
__device__ int   g_nnz[Gg * Nn];
__device__ float g_maskf[Bb * Nn];
__device__ float g_cnt[Bb];
__device__ int   g_mask_mode;

// ---------------- helpers ----------------------------------------------------
__device__ __forceinline__ float f2tf32(float x) {
    uint32_t r;
    asm("cvt.rna.tf32.f32 %0, %1;" : "=r"(r) : "f"(x));
    return __uint_as_float(r);
}
__device__ __forceinline__ uint32_t frag_tf32(float x) {
    uint32_t r;
    asm("cvt.rna.tf32.f32 %0, %1;" : "=r"(r) : "f"(x));
    return r;
}

__device__ __forceinline__ void mma_tf32(float& c0, float& c1, float& c2, float& c3,
                                         uint32_t a0, uint32_t a1, uint32_t a2, uint32_t a3,
                                         uint32_t b0, uint32_t b1) {
    asm volatile(
        "mma.sync.aligned.m16n8k8.row.col.f32.tf32.tf32.f32 "
        "{%0,%1,%2,%3}, {%4,%5,%6,%7}, {%8,%9}, {%0,%1,%2,%3};"
        : "+f"(c0), "+f"(c1), "+f"(c2), "+f"(c3)
        : "r"(a0), "r"(a1), "r"(a2), "r"(a3), "r"(b0), "r"(b1));
}
__device__ __forceinline__ void mma_bf16(float& c0, float& c1, float& c2, float& c3,
                                         uint32_t a0, uint32_t a1, uint32_t a2, uint32_t a3,
                                         uint32_t b0, uint32_t b1) {
    asm volatile(
        "mma.sync.aligned.m16n8k16.row.col.f32.bf16.bf16.f32 "
        "{%0,%1,%2,%3}, {%4,%5,%6,%7}, {%8,%9}, {%0,%1,%2,%3};"
        : "+f"(c0), "+f"(c1), "+f"(c2), "+f"(c3)
        : "r"(a0), "r"(a1), "r"(a2), "r"(a3), "r"(b0), "r"(b1));
}

__device__ __forceinline__ void cp16(void* dst_smem, const void* src) {
    uint32_t d = (uint32_t)__cvta_generic_to_shared(dst_smem);
    asm volatile("cp.async.cg.shared.global [%0], [%1], 16;"
                 :: "r"(d), "l"(src) : "memory");
}
#define CP_COMMIT() asm volatile("cp.async.commit_group;" ::: "memory")
#define CP_WAIT0()  asm volatile("cp.async.wait_group 0;" ::: "memory")

// ---------------- prep: zero d_out + detect mask + weight transposes ---------
__global__ void prep_kernel(const unsigned int* __restrict__ m,
                            float* __restrict__ out,
                            const float* __restrict__ Ws,
                            const float* __restrict__ W_in) {
    const int t = threadIdx.y * 32 + threadIdx.x;
    const int bid = blockIdx.x;

    if (bid < Bb) {
        out[(long)bid * 256 + t] = 0.0f;
        if (bid != 0) return;
        __shared__ int sh_f, sh_b;
        if (t == 0) { sh_f = 0; sh_b = 0; }
        __syncthreads();
        int f = 0, b = 0;
        for (int i = t; i < 16384; i += 256) {
            unsigned int w = m[i];
            if (w == 0x3F800000u) f = 1;
            if (w > 1u && (w & ~0x01010101u) == 0u) b = 1;
        }
        if (f) atomicOr(&sh_f, 1);
        if (b) atomicOr(&sh_b, 1);
        __syncthreads();
        if (t == 0) g_mask_mode = sh_f ? 1 : (sh_b ? 2 : 0);
        return;
    }

    __shared__ float tile[32][33];
    int idx = bid - Bb;
    int z = idx >> 6;           // 0..4
    int rem = idx & 63;
    int bx = rem & 7, by = rem >> 3;
    int x = threadIdx.x, y = threadIdx.y;

    if (z < Ll) {
        const float* src = Ws + (long)z * Hh * Hh;
        __nv_bfloat16* dst = reinterpret_cast<__nv_bfloat16*>(g_Wtb) + (long)z * Hh * Hh;
        int k0 = bx * 32, h0 = by * 32;
        #pragma unroll
        for (int j = 0; j < 32; j += 8)
            tile[y + j][x] = src[(long)(k0 + y + j) * Hh + h0 + x];
        __syncthreads();
        #pragma unroll
        for (int j = 0; j < 32; j += 8)
            dst[(long)(h0 + y + j) * Hh + k0 + x] = __float2bfloat16(tile[x][y + j]);
    } else {
        if (bx >= Ff / 32) return;
        int k0 = bx * 32, h0 = by * 32;
        #pragma unroll
        for (int j = 0; j < 32; j += 8)
            tile[y + j][x] = W_in[(long)(k0 + y + j) * Hh + h0 + x];
        __syncthreads();
        #pragma unroll
        for (int j = 0; j < 32; j += 8)
            g_WtIn[(long)(h0 + y + j) * Ff + k0 + x] = f2tf32(tile[x][y + j]);
    }
}

// ---------------- CSR build + mask expand (merged) ---------------------------
__global__ void csr_mask_kernel(const float* __restrict__ Adj,
                                const void* __restrict__ mraw) {
    __shared__ int cnt;
    if (blockIdx.y < Gg) {
        int g = blockIdx.y;
        int n = blockIdx.x;
        long rbase = (long)g * Nn + n;
        const float* row = Adj + rbase * Nn;
        if (threadIdx.x == 0) cnt = 0;
        __syncthreads();
        for (int m = threadIdx.x; m < Nn; m += blockDim.x) {
            float v = row[m];
            if (v != 0.0f) {
                int p = atomicAdd(&cnt, 1);
                if (p < CAP) {
                    g_coff[rbase * CAP + p] = m * (Hh / 2);
                    g_vals[rbase * CAP + p] = v;
                }
            }
        }
        __syncthreads();
        if (threadIdx.x == 0) g_nnz[rbase] = cnt < CAP ? cnt : CAP;
    } else {
        int b = blockIdx.x;
        if (b >= Bb) return;
        int mode = g_mask_mode;
        if (threadIdx.x == 0) cnt = 0;
        __syncthreads();
        int local = 0;
        for (int n = threadIdx.x; n < Nn; n += blockDim.x) {
            long idx = (long)b * Nn + n;
            bool on;
            if (mode == 1)      on = ((const float*)mraw)[idx] != 0.0f;
            else if (mode == 2) on = ((const unsigned char*)mraw)[idx] != 0;
            else                on = ((const int*)mraw)[idx] != 0;
            g_maskf[idx] = on ? 1.0f : 0.0f;
            local += on ? 1 : 0;
        }
        atomicAdd(&cnt, local);
        __syncthreads();
        if (threadIdx.x == 0) g_cnt[b] = (float)(cnt < 1 ? 1 : cnt);
    }
}

// ---------------- single-shot tf32 input GEMM (fp32 A), 128x64, full-K -------
// X0 = relu(xs @ W_in^T + b_in), writes fp32 X0 AND bf16 copy X0b.
// Full K=128 floats resident: A[128][132], B[64][132] fp32 -> 98.9 KB.
#define PITCH 132
#define GEMM32_SMEM ((128 + 64) * PITCH * sizeof(float))

__global__ __launch_bounds__(256)
void mma_gemm_in_kernel(const float* __restrict__ A,
                        const float* __restrict__ Bt,
                        const float* __restrict__ bias) {
    constexpr int KDIM = Ff;            // 128 floats per row
    extern __shared__ float sh[];
    float* As = sh;                     // [128][PITCH]
    float* Bs = sh + 128 * PITCH;       // [64][PITCH]

    const int t = threadIdx.x;
    const int wid = t >> 5, lane = t & 31;
    const int gid = lane >> 2, tig = lane & 3;
    const int wy = wid >> 1, wx = wid & 1;
    const int col0 = blockIdx.x * 64;
    const int row0 = blockIdx.y * 128;
    const int g = blockIdx.z;

    const float* Ag = A + ((long)g * Nn + row0) * KDIM;
    float* Cg = g_X0 + ((long)g * Nn + row0) * Hh;
    uint32_t* Cb = g_X0b + ((long)g * Nn + row0) * (Hh / 2);

    // A: 128 rows x 128 floats = 4096 float4 -> 16 per thread
    #pragma unroll
    for (int i = 0; i < 16; i++) {
        int f = t + i * 256;
        int row = f >> 5, c4 = f & 31;
        cp16(&As[row * PITCH + c4 * 4], &Ag[(long)row * KDIM + c4 * 4]);
    }
    // B: 64 rows x 128 floats = 2048 float4 -> 8 per thread
    #pragma unroll
    for (int i = 0; i < 8; i++) {
        int f = t + i * 256;
        int row = f >> 5, c4 = f & 31;
        cp16(&Bs[row * PITCH + c4 * 4], &Bt[(long)(col0 + row) * KDIM + c4 * 4]);
    }
    CP_COMMIT();
    CP_WAIT0();
    __syncthreads();

    float acc[2][4][4] = {};
    #pragma unroll
    for (int c = 0; c < KDIM / 32; c++) {
        #pragma unroll
        for (int ks = 0; ks < 4; ks++) {
            const int kk = c * 32 + ks * 8 + tig;
            uint32_t a[2][4];
            #pragma unroll
            for (int mt = 0; mt < 2; mt++) {
                int mr = wy * 32 + mt * 16 + gid;
                a[mt][0] = frag_tf32(As[(mr    ) * PITCH + kk]);
                a[mt][1] = frag_tf32(As[(mr + 8) * PITCH + kk]);
                a[mt][2] = frag_tf32(As[(mr    ) * PITCH + kk + 4]);
                a[mt][3] = frag_tf32(As[(mr + 8) * PITCH + kk + 4]);
            }
            uint32_t b[4][2];
            #pragma unroll
            for (int nt = 0; nt < 4; nt++) {
                int nr = wx * 32 + nt * 8 + gid;
                b[nt][0] = __float_as_uint(Bs[nr * PITCH + kk]);
                b[nt][1] = __float_as_uint(Bs[nr * PITCH + kk + 4]);
            }
            #pragma unroll
            for (int mt = 0; mt < 2; mt++)
                #pragma unroll
                for (int nt = 0; nt < 4; nt++)
                    mma_tf32(acc[mt][nt][0], acc[mt][nt][1],
                             acc[mt][nt][2], acc[mt][nt][3],
                             a[mt][0], a[mt][1], a[mt][2], a[mt][3],
                             b[nt][0], b[nt][1]);
        }
    }

    #pragma unroll
    for (int mt = 0; mt < 2; mt++) {
        int r = wy * 32 + mt * 16 + gid;
        #pragma unroll
        for (int nt = 0; nt < 4; nt++) {
            int cc = col0 + wx * 32 + nt * 8 + 2 * tig;
            float b0 = bias[cc], b1 = bias[cc + 1];
            float v0 = fmaxf(acc[mt][nt][0] + b0, 0.f);
            float v1 = fmaxf(acc[mt][nt][1] + b1, 0.f);
            float v2 = fmaxf(acc[mt][nt][2] + b0, 0.f);
            float v3 = fmaxf(acc[mt][nt][3] + b1, 0.f);
            *reinterpret_cast<float2*>(&Cg[(long)r * Hh + cc]) = make_float2(v0, v1);
            *reinterpret_cast<float2*>(&Cg[(long)(r + 8) * Hh + cc]) = make_float2(v2, v3);
            __nv_bfloat162 p0 = __float22bfloat162_rn(make_float2(v0, v1));
            __nv_bfloat162 p1 = __float22bfloat162_rn(make_float2(v2, v3));
            Cb[(long)r * (Hh / 2) + cc / 2]       = *reinterpret_cast<uint32_t*>(&p0);
            Cb[(long)(r + 8) * (Hh / 2) + cc / 2] = *reinterpret_cast<uint32_t*>(&p1);
        }
    }
}

// ---------------- single-shot bf16 layer GEMM: Yb = Xb @ Wtb^T ----------------
// Full K=256 bf16 (=128 words) resident: A[128][132], B[64][132] words -> 98.9 KB.
#define GEMM16_SMEM ((128 + 64) * PITCH * sizeof(uint32_t))

__global__ __launch_bounds__(256)
void mma_gemm_bf16_kernel(const uint32_t* __restrict__ A,   // bf16x2 words
                          const uint32_t* __restrict__ Bt,  // bf16x2 words
                          uint32_t* __restrict__ Yout) {
    constexpr int KW = Hh / 2;       // 128 words per row
    extern __shared__ uint32_t shw[];
    uint32_t* As = shw;                  // [128][PITCH]
    uint32_t* Bs = shw + 128 * PITCH;    // [64][PITCH]

    const int t = threadIdx.x;
    const int wid = t >> 5, lane = t & 31;
    const int gid = lane >> 2, tig = lane & 3;
    const int wy = wid >> 1, wx = wid & 1;
    const int col0 = blockIdx.x * 64;
    const int row0 = blockIdx.y * 128;
    const int g = blockIdx.z;

    const uint32_t* Ag = A + ((long)g * Nn + row0) * KW;
    uint32_t* Yb = Yout + ((long)g * Nn + row0) * (Hh / 2);

    // A: 128 rows x 128 words = 4096 x16B -> 16 per thread
    #pragma unroll
    for (int i = 0; i < 16; i++) {
        int f = t + i * 256;
        int row = f >> 5, c4 = f & 31;
        cp16(&As[row * PITCH + c4 * 4], &Ag[(long)row * KW + c4 * 4]);
    }
    // B: 64 rows x 128 words = 2048 x16B -> 8 per thread
    #pragma unroll
    for (int i = 0; i < 8; i++) {
        int f = t + i * 256;
        int row = f >> 5, c4 = f & 31;
        cp16(&Bs[row * PITCH + c4 * 4], &Bt[(long)(col0 + row) * KW + c4 * 4]);
    }
    CP_COMMIT();
    CP_WAIT0();
    __syncthreads();

    float acc[2][4][4] = {};
    #pragma unroll
    for (int c = 0; c < 8; c++) {            // 8 chunks of 16 words (32 bf16)
        #pragma unroll
        for (int ks = 0; ks < 2; ks++) {
            const int kw = c * 16 + ks * 8 + tig;
            uint32_t a[2][4];
            #pragma unroll
            for (int mt = 0; mt < 2; mt++) {
                int mr = wy * 32 + mt * 16 + gid;
                a[mt][0] = As[(mr    ) * PITCH + kw];
                a[mt][1] = As[(mr + 8) * PITCH + kw];
                a[mt][2] = As[(mr    ) * PITCH + kw + 4];
                a[mt][3] = As[(mr + 8) * PITCH + kw + 4];
            }
            uint32_t b[4][2];
            #pragma unroll
            for (int nt = 0; nt < 4; nt++) {
                int nr = wx * 32 + nt * 8 + gid;
                b[nt][0] = Bs[nr * PITCH + kw];
                b[nt][1] = Bs[nr * PITCH + kw + 4];
            }
            #pragma unroll
            for (int mt = 0; mt < 2; mt++)
                #pragma unroll
                for (int nt = 0; nt < 4; nt++)
                    mma_bf16(acc[mt][nt][0], acc[mt][nt][1],
                             acc[mt][nt][2], acc[mt][nt][3],
                             a[mt][0], a[mt][1], a[mt][2], a[mt][3],
                             b[nt][0], b[nt][1]);
        }
    }

    #pragma unroll
    for (int mt = 0; mt < 2; mt++) {
        int r = wy * 32 + mt * 16 + gid;
        #pragma unroll
        for (int nt = 0; nt < 4; nt++) {
            int cc = col0 + wx * 32 + nt * 8 + 2 * tig;
            __nv_bfloat162 p0 = __float22bfloat162_rn(
                make_float2(acc[mt][nt][0], acc[mt][nt][1]));
            __nv_bfloat162 p1 = __float22bfloat162_rn(
                make_float2(acc[mt][nt][2], acc[mt][nt][3]));
            Yb[(long)r * (Hh / 2) + cc / 2]       = *reinterpret_cast<uint32_t*>(&p0);
            Yb[(long)(r + 8) * (Hh / 2) + cc / 2] = *reinterpret_cast<uint32_t*>(&p1);
        }
    }
}

// ---------------- SpMM: X = act(A_sparse @ Yb + bias) ------------------------
template<bool LAST>
__global__ __launch_bounds__(128)
void spmm_kernel(const float* __restrict__ bias) {
    int g = blockIdx.y;
    int n = blockIdx.x;
    int t = threadIdx.x;
    int lane = t & 31, wid = t >> 5;
    long rbase = (long)g * Nn + n;
    int nnz = g_nnz[rbase];

    __shared__ int   soff[CAP];
    __shared__ float sval[CAP];
    for (int j = t; j < nnz; j += 128) {
        soff[j] = g_coff[rbase * CAP + j];
        sval[j] = g_vals[rbase * CAP + j];
    }
    __syncthreads();

    const uint32_t* Yt = g_Yb + (long)g * Nn * (Hh / 2) + t;   // hoist +t
    float a0 = 0.f, a1 = 0.f;
    int j = 0;
    for (; j + 8 <= nnz; j += 8) {
        uint32_t w[8];
        #pragma unroll
        for (int q = 0; q < 8; q++)
            w[q] = Yt[soff[j + q]];
        #pragma unroll
        for (int q = 0; q < 8; q++) {
            float2 f = __bfloat1622float2(*reinterpret_cast<__nv_bfloat162*>(&w[q]));
            a0 += sval[j + q] * f.x;
            a1 += sval[j + q] * f.y;
        }
    }
    if (j + 4 <= nnz) {
        uint32_t w[4];
        #pragma unroll
        for (int q = 0; q < 4; q++)
            w[q] = Yt[soff[j + q]];
        #pragma unroll
        for (int q = 0; q < 4; q++) {
            float2 f = __bfloat1622float2(*reinterpret_cast<__nv_bfloat162*>(&w[q]));
            a0 += sval[j + q] * f.x;
            a1 += sval[j + q] * f.y;
        }
        j += 4;
    }
    for (; j < nnz; j++) {
        uint32_t w = Yt[soff[j]];
        float2 f = __bfloat1622float2(*reinterpret_cast<__nv_bfloat162*>(&w));
        a0 += sval[j] * f.x;
        a1 += sval[j] * f.y;
    }

    float2 bv = *reinterpret_cast<const float2*>(&bias[2 * t]);
    float v0 = a0 + bv.x, v1 = a1 + bv.y;

    if (!LAST) {
        __nv_bfloat162 p = __float22bfloat162_rn(
            make_float2(fmaxf(v0, 0.f), fmaxf(v1, 0.f)));
        g_Xb[rbase * (Hh / 2) + t] = *reinterpret_cast<uint32_t*>(&p);
    } else {
        __shared__ float smax[4], ssum[4];
        float m = fmaxf(v0, v1);
        #pragma unroll
        for (int off = 16; off > 0; off >>= 1)
            m = fmaxf(m, __shfl_xor_sync(0xFFFFFFFFu, m, off));
        if (lane == 0) smax[wid] = m;
        __syncthreads();
        m = fmaxf(fmaxf(smax[0], smax[1]), fmaxf(smax[2], smax[3]));
        float e0 = expf(v0 - m), e1 = expf(v1 - m);
        float s = e0 + e1;
        #pragma unroll
        for (int off = 16; off > 0; off >>= 1)
            s += __shfl_xor_sync(0xFFFFFFFFu, s, off);
        if (lane == 0) ssum[wid] = s;
        __syncthreads();
        s = (ssum[0] + ssum[1]) + (ssum[2] + ssum[3]);
        float inv = 1.0f / s;
        float2 x0 = reinterpret_cast<const float2*>(g_X0)[rbase * (Hh / 2) + t];
        reinterpret_cast<float2*>(g_X)[rbase * (Hh / 2) + t] =
            make_float2(e0 * inv + x0.x, e1 * inv + x0.y);
    }
}

// ---------------- per-sample masked mean -------------------------------------
__global__ void masked_mean_kernel(const int* __restrict__ graph,
                                   float* __restrict__ out) {
    int b = blockIdx.x;
    int chunk = blockIdx.y;
    int h = threadIdx.x;
    int g = graph[b];
    const float* xg = g_X + ((long)g * Nn + chunk * 128) * Hh;
    const float* mb = g_maskf + (long)b * Nn + chunk * 128;
    float acc = 0.f;
    #pragma unroll 4
    for (int n = 0; n < 128; n++) {
        float mv = mb[n];
        if (mv != 0.f) acc += xg[(long)n * Hh + h];
    }
    atomicAdd(&out[(long)b * Hh + h], acc / g_cnt[b]);
}

// ---------------- launch -----------------------------------------------------
extern "C" void kernel_launch(void* const* d_in, const int* in_sizes, int n_in,
                              void* d_out, int out_size) {
    const int*   graph = (const int*)  d_in[0];
    const void*  mask  =               d_in[1];
    const float* xs    = (const float*)d_in[2];
    const float* Adj   = (const float*)d_in[3];
    const float* W_in  = (const float*)d_in[4];
    const float* b_in  = (const float*)d_in[5];
    const float* Ws    = (const float*)d_in[6];
    const float* bs    = (const float*)d_in[7];
    float* out = (float*)d_out;

    float *pWtIn;
    uint32_t *pX0b, *pXb, *pYb, *pWtb;
    cudaGetSymbolAddress((void**)&pWtIn, g_WtIn);
    cudaGetSymbolAddress((void**)&pX0b,  g_X0b);
    cudaGetSymbolAddress((void**)&pXb,   g_Xb);
    cudaGetSymbolAddress((void**)&pYb,   g_Yb);
    cudaGetSymbolAddress((void**)&pWtb,  g_Wtb);

    cudaFuncSetAttribute(mma_gemm_in_kernel,
        cudaFuncAttributeMaxDynamicSharedMemorySize, (int)GEMM32_SMEM);
    cudaFuncSetAttribute(mma_gemm_bf16_kernel,
        cudaFuncAttributeMaxDynamicSharedMemorySize, (int)GEMM16_SMEM);

    // prep: zero d_out + detect mask dtype + weight transposes
    prep_kernel<<<Bb + 320, dim3(32, 8)>>>((const unsigned int*)mask, out, Ws, W_in);

    // CSR build (precomputed offsets) + mask expand
    dim3 cm_grid(Nn, Gg + 1);
    csr_mask_kernel<<<cm_grid, 256>>>(Adj, mask);

    dim3 ggrid(Hh / 64, Nn / 128, Gg);   // 256 CTAs

    // X0 = relu(xs @ W_in + b_in)  [tf32; fp32 + bf16 copies]
    mma_gemm_in_kernel<<<ggrid, 256, GEMM32_SMEM>>>(xs, pWtIn, b_in);

    dim3 sp_grid(Nn, Gg);
    const uint32_t* xin = pX0b;
    for (int i = 0; i < Ll; i++) {
        mma_gemm_bf16_kernel<<<ggrid, 256, GEMM16_SMEM>>>(
            xin, pWtb + (long)i * Hh * Hh / 2, pYb);
        if (i < Ll - 1)
            spmm_kernel<false><<<sp_grid, 128>>>(bs + (long)i * Hh);
        else
            spmm_kernel<true><<<sp_grid, 128>>>(bs + (long)i * Hh);
        xin = pXb;
    }

    dim3 mm_grid(Bb, Nn / 128);
    masked_mean_kernel<<<mm_grid, Hh>>>(graph, out);
}

// round 13
// speedup vs baseline: 1.4811x; 1.0449x over previous
#include <cuda_runtime.h>
#include <cuda_bf16.h>
#include <cstdint>

// Problem constants
#define Gg 8
#define Nn 1024
#define Ff 128
#define Hh 256
#define Ll 4
#define Bb 64
#define CAP 128

// ---------------- scratch (device globals) ----------------------------------
__device__ __align__(16) float    g_X0 [Gg * Nn * Hh];          // fp32 residual
__device__ __align__(16) uint32_t g_X0b[Gg * Nn * Hh / 2];      // bf16x2 copy of X0
__device__ __align__(16) float    g_X  [Gg * Nn * Hh];          // fp32 final x
__device__ __align__(16) uint32_t g_Xb [Gg * Nn * Hh / 2];      // bf16x2 inter-layer x
__device__ __align__(16) uint32_t g_Yb [Gg * Nn * Hh / 2];      // bf16x2 Y = x @ W
__device__ __align__(16) uint32_t g_Wtb[Ll * Hh * Hh / 2];      // bf16x2 Ws^T [l][n][k]
__device__ __align__(16) float    g_WtIn[Hh * Ff];              // W_in^T (tf32-rounded)
__device__ __align__(16) int      g_coff[(long)Gg * Nn * CAP];  // precomputed col*64 (uint2 idx)
__device__ __align__(16) float    g_vals[(long)Gg * Nn * CAP];
__device__ int   g_nnz[Gg * Nn];
__device__ float g_maskf[Bb * Nn];
__device__ float g_cnt[Bb];
__device__ int   g_mask_mode;

// ---------------- helpers ----------------------------------------------------
__device__ __forceinline__ float f2tf32(float x) {
    uint32_t r;
    asm("cvt.rna.tf32.f32 %0, %1;" : "=r"(r) : "f"(x));
    return __uint_as_float(r);
}
__device__ __forceinline__ uint32_t frag_tf32(float x) {
    uint32_t r;
    asm("cvt.rna.tf32.f32 %0, %1;" : "=r"(r) : "f"(x));
    return r;
}

__device__ __forceinline__ void mma_tf32(float& c0, float& c1, float& c2, float& c3,
                                         uint32_t a0, uint32_t a1, uint32_t a2, uint32_t a3,
                                         uint32_t b0, uint32_t b1) {
    asm volatile(
        "mma.sync.aligned.m16n8k8.row.col.f32.tf32.tf32.f32 "
        "{%0,%1,%2,%3}, {%4,%5,%6,%7}, {%8,%9}, {%0,%1,%2,%3};"
        : "+f"(c0), "+f"(c1), "+f"(c2), "+f"(c3)
        : "r"(a0), "r"(a1), "r"(a2), "r"(a3), "r"(b0), "r"(b1));
}
__device__ __forceinline__ void mma_bf16(float& c0, float& c1, float& c2, float& c3,
                                         uint32_t a0, uint32_t a1, uint32_t a2, uint32_t a3,
                                         uint32_t b0, uint32_t b1) {
    asm volatile(
        "mma.sync.aligned.m16n8k16.row.col.f32.bf16.bf16.f32 "
        "{%0,%1,%2,%3}, {%4,%5,%6,%7}, {%8,%9}, {%0,%1,%2,%3};"
        : "+f"(c0), "+f"(c1), "+f"(c2), "+f"(c3)
        : "r"(a0), "r"(a1), "r"(a2), "r"(a3), "r"(b0), "r"(b1));
}

__device__ __forceinline__ void cp16(void* dst_smem, const void* src) {
    uint32_t d = (uint32_t)__cvta_generic_to_shared(dst_smem);
    asm volatile("cp.async.cg.shared.global [%0], [%1], 16;"
                 :: "r"(d), "l"(src) : "memory");
}
#define CP_COMMIT() asm volatile("cp.async.commit_group;" ::: "memory")
#define CP_WAIT0()  asm volatile("cp.async.wait_group 0;" ::: "memory")

// ---------------- prep: zero d_out + detect mask + weight transposes ---------
__global__ void prep_kernel(const unsigned int* __restrict__ m,
                            float* __restrict__ out,
                            const float* __restrict__ Ws,
                            const float* __restrict__ W_in) {
    const int t = threadIdx.y * 32 + threadIdx.x;
    const int bid = blockIdx.x;

    if (bid < Bb) {
        out[(long)bid * 256 + t] = 0.0f;
        if (bid != 0) return;
        __shared__ int sh_f, sh_b;
        if (t == 0) { sh_f = 0; sh_b = 0; }
        __syncthreads();
        int f = 0, b = 0;
        for (int i = t; i < 16384; i += 256) {
            unsigned int w = m[i];
            if (w == 0x3F800000u) f = 1;
            if (w > 1u && (w & ~0x01010101u) == 0u) b = 1;
        }
        if (f) atomicOr(&sh_f, 1);
        if (b) atomicOr(&sh_b, 1);
        __syncthreads();
        if (t == 0) g_mask_mode = sh_f ? 1 : (sh_b ? 2 : 0);
        return;
    }

    __shared__ float tile[32][33];
    int idx = bid - Bb;
    int z = idx >> 6;           // 0..4
    int rem = idx & 63;
    int bx = rem & 7, by = rem >> 3;
    int x = threadIdx.x, y = threadIdx.y;

    if (z < Ll) {
        const float* src = Ws + (long)z * Hh * Hh;
        __nv_bfloat16* dst = reinterpret_cast<__nv_bfloat16*>(g_Wtb) + (long)z * Hh * Hh;
        int k0 = bx * 32, h0 = by * 32;
        #pragma unroll
        for (int j = 0; j < 32; j += 8)
            tile[y + j][x] = src[(long)(k0 + y + j) * Hh + h0 + x];
        __syncthreads();
        #pragma unroll
        for (int j = 0; j < 32; j += 8)
            dst[(long)(h0 + y + j) * Hh + k0 + x] = __float2bfloat16(tile[x][y + j]);
    } else {
        if (bx >= Ff / 32) return;
        int k0 = bx * 32, h0 = by * 32;
        #pragma unroll
        for (int j = 0; j < 32; j += 8)
            tile[y + j][x] = W_in[(long)(k0 + y + j) * Hh + h0 + x];
        __syncthreads();
        #pragma unroll
        for (int j = 0; j < 32; j += 8)
            g_WtIn[(long)(h0 + y + j) * Ff + k0 + x] = f2tf32(tile[x][y + j]);
    }
}

// ---------------- CSR build + mask expand (merged) ---------------------------
// Adjacency scanned as float4; CSR stores uint2 offsets (col * 64).
__global__ void csr_mask_kernel(const float* __restrict__ Adj,
                                const void* __restrict__ mraw) {
    __shared__ int cnt;
    if (blockIdx.y < Gg) {
        int g = blockIdx.y;
        int n = blockIdx.x;
        long rbase = (long)g * Nn + n;
        const float4* row4 = reinterpret_cast<const float4*>(Adj + rbase * Nn);
        if (threadIdx.x == 0) cnt = 0;
        __syncthreads();
        float4 v4 = row4[threadIdx.x];   // 256 threads x 4 = 1024 cols
        int mbase = threadIdx.x * 4;
        #pragma unroll
        for (int c = 0; c < 4; c++) {
            float v = (c == 0) ? v4.x : (c == 1) ? v4.y : (c == 2) ? v4.z : v4.w;
            if (v != 0.0f) {
                int p = atomicAdd(&cnt, 1);
                if (p < CAP) {
                    g_coff[rbase * CAP + p] = (mbase + c) * 64;
                    g_vals[rbase * CAP + p] = v;
                }
            }
        }
        __syncthreads();
        if (threadIdx.x == 0) g_nnz[rbase] = cnt < CAP ? cnt : CAP;
    } else {
        int b = blockIdx.x;
        if (b >= Bb) return;
        int mode = g_mask_mode;
        if (threadIdx.x == 0) cnt = 0;
        __syncthreads();
        int local = 0;
        for (int n = threadIdx.x; n < Nn; n += blockDim.x) {
            long idx = (long)b * Nn + n;
            bool on;
            if (mode == 1)      on = ((const float*)mraw)[idx] != 0.0f;
            else if (mode == 2) on = ((const unsigned char*)mraw)[idx] != 0;
            else                on = ((const int*)mraw)[idx] != 0;
            g_maskf[idx] = on ? 1.0f : 0.0f;
            local += on ? 1 : 0;
        }
        atomicAdd(&cnt, local);
        __syncthreads();
        if (threadIdx.x == 0) g_cnt[b] = (float)(cnt < 1 ? 1 : cnt);
    }
}

// ---------------- single-shot tf32 input GEMM (fp32 A), 128x64, full-K -------
#define PITCH 132
#define GEMM32_SMEM ((128 + 64) * PITCH * sizeof(float))

__global__ __launch_bounds__(256)
void mma_gemm_in_kernel(const float* __restrict__ A,
                        const float* __restrict__ Bt,
                        const float* __restrict__ bias) {
    constexpr int KDIM = Ff;
    extern __shared__ float sh[];
    float* As = sh;
    float* Bs = sh + 128 * PITCH;

    const int t = threadIdx.x;
    const int wid = t >> 5, lane = t & 31;
    const int gid = lane >> 2, tig = lane & 3;
    const int wy = wid >> 1, wx = wid & 1;
    const int col0 = blockIdx.x * 64;
    const int row0 = blockIdx.y * 128;
    const int g = blockIdx.z;

    const float* Ag = A + ((long)g * Nn + row0) * KDIM;
    float* Cg = g_X0 + ((long)g * Nn + row0) * Hh;
    uint32_t* Cb = g_X0b + ((long)g * Nn + row0) * (Hh / 2);

    #pragma unroll
    for (int i = 0; i < 16; i++) {
        int f = t + i * 256;
        int row = f >> 5, c4 = f & 31;
        cp16(&As[row * PITCH + c4 * 4], &Ag[(long)row * KDIM + c4 * 4]);
    }
    #pragma unroll
    for (int i = 0; i < 8; i++) {
        int f = t + i * 256;
        int row = f >> 5, c4 = f & 31;
        cp16(&Bs[row * PITCH + c4 * 4], &Bt[(long)(col0 + row) * KDIM + c4 * 4]);
    }
    CP_COMMIT();
    CP_WAIT0();
    __syncthreads();

    float acc[2][4][4] = {};
    #pragma unroll
    for (int c = 0; c < KDIM / 32; c++) {
        #pragma unroll
        for (int ks = 0; ks < 4; ks++) {
            const int kk = c * 32 + ks * 8 + tig;
            uint32_t a[2][4];
            #pragma unroll
            for (int mt = 0; mt < 2; mt++) {
                int mr = wy * 32 + mt * 16 + gid;
                a[mt][0] = frag_tf32(As[(mr    ) * PITCH + kk]);
                a[mt][1] = frag_tf32(As[(mr + 8) * PITCH + kk]);
                a[mt][2] = frag_tf32(As[(mr    ) * PITCH + kk + 4]);
                a[mt][3] = frag_tf32(As[(mr + 8) * PITCH + kk + 4]);
            }
            uint32_t b[4][2];
            #pragma unroll
            for (int nt = 0; nt < 4; nt++) {
                int nr = wx * 32 + nt * 8 + gid;
                b[nt][0] = __float_as_uint(Bs[nr * PITCH + kk]);
                b[nt][1] = __float_as_uint(Bs[nr * PITCH + kk + 4]);
            }
            #pragma unroll
            for (int mt = 0; mt < 2; mt++)
                #pragma unroll
                for (int nt = 0; nt < 4; nt++)
                    mma_tf32(acc[mt][nt][0], acc[mt][nt][1],
                             acc[mt][nt][2], acc[mt][nt][3],
                             a[mt][0], a[mt][1], a[mt][2], a[mt][3],
                             b[nt][0], b[nt][1]);
        }
    }

    #pragma unroll
    for (int mt = 0; mt < 2; mt++) {
        int r = wy * 32 + mt * 16 + gid;
        #pragma unroll
        for (int nt = 0; nt < 4; nt++) {
            int cc = col0 + wx * 32 + nt * 8 + 2 * tig;
            float b0 = bias[cc], b1 = bias[cc + 1];
            float v0 = fmaxf(acc[mt][nt][0] + b0, 0.f);
            float v1 = fmaxf(acc[mt][nt][1] + b1, 0.f);
            float v2 = fmaxf(acc[mt][nt][2] + b0, 0.f);
            float v3 = fmaxf(acc[mt][nt][3] + b1, 0.f);
            *reinterpret_cast<float2*>(&Cg[(long)r * Hh + cc]) = make_float2(v0, v1);
            *reinterpret_cast<float2*>(&Cg[(long)(r + 8) * Hh + cc]) = make_float2(v2, v3);
            __nv_bfloat162 p0 = __float22bfloat162_rn(make_float2(v0, v1));
            __nv_bfloat162 p1 = __float22bfloat162_rn(make_float2(v2, v3));
            Cb[(long)r * (Hh / 2) + cc / 2]       = *reinterpret_cast<uint32_t*>(&p0);
            Cb[(long)(r + 8) * (Hh / 2) + cc / 2] = *reinterpret_cast<uint32_t*>(&p1);
        }
    }
}

// ---------------- single-shot bf16 layer GEMM: Yb = Xb @ Wtb^T ----------------
#define GEMM16_SMEM ((128 + 64) * PITCH * sizeof(uint32_t))

__global__ __launch_bounds__(256)
void mma_gemm_bf16_kernel(const uint32_t* __restrict__ A,
                          const uint32_t* __restrict__ Bt,
                          uint32_t* __restrict__ Yout) {
    constexpr int KW = Hh / 2;
    extern __shared__ uint32_t shw[];
    uint32_t* As = shw;
    uint32_t* Bs = shw + 128 * PITCH;

    const int t = threadIdx.x;
    const int wid = t >> 5, lane = t & 31;
    const int gid = lane >> 2, tig = lane & 3;
    const int wy = wid >> 1, wx = wid & 1;
    const int col0 = blockIdx.x * 64;
    const int row0 = blockIdx.y * 128;
    const int g = blockIdx.z;

    const uint32_t* Ag = A + ((long)g * Nn + row0) * KW;
    uint32_t* Yb = Yout + ((long)g * Nn + row0) * (Hh / 2);

    #pragma unroll
    for (int i = 0; i < 16; i++) {
        int f = t + i * 256;
        int row = f >> 5, c4 = f & 31;
        cp16(&As[row * PITCH + c4 * 4], &Ag[(long)row * KW + c4 * 4]);
    }
    #pragma unroll
    for (int i = 0; i < 8; i++) {
        int f = t + i * 256;
        int row = f >> 5, c4 = f & 31;
        cp16(&Bs[row * PITCH + c4 * 4], &Bt[(long)(col0 + row) * KW + c4 * 4]);
    }
    CP_COMMIT();
    CP_WAIT0();
    __syncthreads();

    float acc[2][4][4] = {};
    #pragma unroll
    for (int c = 0; c < 8; c++) {
        #pragma unroll
        for (int ks = 0; ks < 2; ks++) {
            const int kw = c * 16 + ks * 8 + tig;
            uint32_t a[2][4];
            #pragma unroll
            for (int mt = 0; mt < 2; mt++) {
                int mr = wy * 32 + mt * 16 + gid;
                a[mt][0] = As[(mr    ) * PITCH + kw];
                a[mt][1] = As[(mr + 8) * PITCH + kw];
                a[mt][2] = As[(mr    ) * PITCH + kw + 4];
                a[mt][3] = As[(mr + 8) * PITCH + kw + 4];
            }
            uint32_t b[4][2];
            #pragma unroll
            for (int nt = 0; nt < 4; nt++) {
                int nr = wx * 32 + nt * 8 + gid;
                b[nt][0] = Bs[nr * PITCH + kw];
                b[nt][1] = Bs[nr * PITCH + kw + 4];
            }
            #pragma unroll
            for (int mt = 0; mt < 2; mt++)
                #pragma unroll
                for (int nt = 0; nt < 4; nt++)
                    mma_bf16(acc[mt][nt][0], acc[mt][nt][1],
                             acc[mt][nt][2], acc[mt][nt][3],
                             a[mt][0], a[mt][1], a[mt][2], a[mt][3],
                             b[nt][0], b[nt][1]);
        }
    }

    #pragma unroll
    for (int mt = 0; mt < 2; mt++) {
        int r = wy * 32 + mt * 16 + gid;
        #pragma unroll
        for (int nt = 0; nt < 4; nt++) {
            int cc = col0 + wx * 32 + nt * 8 + 2 * tig;
            __nv_bfloat162 p0 = __float22bfloat162_rn(
                make_float2(acc[mt][nt][0], acc[mt][nt][1]));
            __nv_bfloat162 p1 = __float22bfloat162_rn(
                make_float2(acc[mt][nt][2], acc[mt][nt][3]));
            Yb[(long)r * (Hh / 2) + cc / 2]       = *reinterpret_cast<uint32_t*>(&p0);
            Yb[(long)(r + 8) * (Hh / 2) + cc / 2] = *reinterpret_cast<uint32_t*>(&p1);
        }
    }
}

// ---------------- SpMM: X = act(A_sparse @ Yb + bias) ------------------------
// 128 threads = 2 groups of 64; group p handles neighbors j === p (mod 2).
// Thread u in each group owns h-quad [4u, 4u+4) via uint2 (4 bf16) gathers.
template<bool LAST>
__global__ __launch_bounds__(128)
void spmm_kernel(const float* __restrict__ bias) {
    int g = blockIdx.y;
    int n = blockIdx.x;
    int t = threadIdx.x;
    int grp = t >> 6, u = t & 63;
    int lane = t & 31, wid = t >> 5;
    long rbase = (long)g * Nn + n;
    int nnz = g_nnz[rbase];

    __shared__ int   soff[CAP];
    __shared__ float sval[CAP];
    for (int j = t; j < nnz; j += 128) {
        soff[j] = g_coff[rbase * CAP + j];
        sval[j] = g_vals[rbase * CAP + j];
    }
    __syncthreads();

    const uint2* Yu = reinterpret_cast<const uint2*>(
        g_Yb + (long)g * Nn * (Hh / 2)) + u;
    float a0 = 0.f, a1 = 0.f, a2 = 0.f, a3 = 0.f;
    int j = grp;
    for (; j + 14 < nnz; j += 16) {          // 8 neighbors per group per batch
        uint2 w[8];
        #pragma unroll
        for (int q = 0; q < 8; q++)
            w[q] = Yu[soff[j + 2 * q]];
        #pragma unroll
        for (int q = 0; q < 8; q++) {
            float s = sval[j + 2 * q];
            float2 f0 = __bfloat1622float2(*reinterpret_cast<__nv_bfloat162*>(&w[q].x));
            float2 f1 = __bfloat1622float2(*reinterpret_cast<__nv_bfloat162*>(&w[q].y));
            a0 += s * f0.x; a1 += s * f0.y;
            a2 += s * f1.x; a3 += s * f1.y;
        }
    }
    for (; j < nnz; j += 2) {
        uint2 w = Yu[soff[j]];
        float s = sval[j];
        float2 f0 = __bfloat1622float2(*reinterpret_cast<__nv_bfloat162*>(&w.x));
        float2 f1 = __bfloat1622float2(*reinterpret_cast<__nv_bfloat162*>(&w.y));
        a0 += s * f0.x; a1 += s * f0.y;
        a2 += s * f1.x; a3 += s * f1.y;
    }

    // combine the two neighbor groups
    __shared__ float4 red[64];
    if (grp == 1) red[u] = make_float4(a0, a1, a2, a3);
    __syncthreads();
    if (grp == 0) {
        float4 r = red[u];
        a0 += r.x; a1 += r.y; a2 += r.z; a3 += r.w;
    }

    if (!LAST) {
        if (grp == 0) {
            float4 bv = *reinterpret_cast<const float4*>(&bias[4 * u]);
            float v0 = fmaxf(a0 + bv.x, 0.f);
            float v1 = fmaxf(a1 + bv.y, 0.f);
            float v2 = fmaxf(a2 + bv.z, 0.f);
            float v3 = fmaxf(a3 + bv.w, 0.f);
            __nv_bfloat162 p0 = __float22bfloat162_rn(make_float2(v0, v1));
            __nv_bfloat162 p1 = __float22bfloat162_rn(make_float2(v2, v3));
            uint2 o;
            o.x = *reinterpret_cast<uint32_t*>(&p0);
            o.y = *reinterpret_cast<uint32_t*>(&p1);
            reinterpret_cast<uint2*>(g_Xb)[rbase * 64 + u] = o;
        }
    } else {
        float v0 = 0.f, v1 = 0.f, v2 = 0.f, v3 = 0.f;
        float m = -1e30f;
        if (grp == 0) {
            float4 bv = *reinterpret_cast<const float4*>(&bias[4 * u]);
            v0 = a0 + bv.x; v1 = a1 + bv.y; v2 = a2 + bv.z; v3 = a3 + bv.w;
            m = fmaxf(fmaxf(v0, v1), fmaxf(v2, v3));
        }
        #pragma unroll
        for (int off = 16; off > 0; off >>= 1)
            m = fmaxf(m, __shfl_xor_sync(0xFFFFFFFFu, m, off));
        __shared__ float smax[4], ssum[4];
        if (lane == 0) smax[wid] = m;
        __syncthreads();
        m = fmaxf(smax[0], smax[1]);   // warps 0,1 are group 0
        float e0 = 0.f, e1 = 0.f, e2 = 0.f, e3 = 0.f, s = 0.f;
        if (grp == 0) {
            e0 = expf(v0 - m); e1 = expf(v1 - m);
            e2 = expf(v2 - m); e3 = expf(v3 - m);
            s = (e0 + e1) + (e2 + e3);
        }
        #pragma unroll
        for (int off = 16; off > 0; off >>= 1)
            s += __shfl_xor_sync(0xFFFFFFFFu, s, off);
        if (lane == 0) ssum[wid] = s;
        __syncthreads();
        s = ssum[0] + ssum[1];
        if (grp == 0) {
            float inv = 1.0f / s;
            float4 x0 = reinterpret_cast<const float4*>(g_X0)[rbase * 64 + u];
            reinterpret_cast<float4*>(g_X)[rbase * 64 + u] =
                make_float4(e0 * inv + x0.x, e1 * inv + x0.y,
                            e2 * inv + x0.z, e3 * inv + x0.w);
        }
    }
}

// ---------------- per-sample masked mean -------------------------------------
__global__ void masked_mean_kernel(const int* __restrict__ graph,
                                   float* __restrict__ out) {
    int b = blockIdx.x;
    int chunk = blockIdx.y;
    int h = threadIdx.x;
    int g = graph[b];
    const float* xg = g_X + ((long)g * Nn + chunk * 128) * Hh;
    const float* mb = g_maskf + (long)b * Nn + chunk * 128;
    float acc = 0.f;
    #pragma unroll 4
    for (int n = 0; n < 128; n++) {
        float mv = mb[n];
        if (mv != 0.f) acc += xg[(long)n * Hh + h];
    }
    atomicAdd(&out[(long)b * Hh + h], acc / g_cnt[b]);
}

// ---------------- launch -----------------------------------------------------
extern "C" void kernel_launch(void* const* d_in, const int* in_sizes, int n_in,
                              void* d_out, int out_size) {
    const int*   graph = (const int*)  d_in[0];
    const void*  mask  =               d_in[1];
    const float* xs    = (const float*)d_in[2];
    const float* Adj   = (const float*)d_in[3];
    const float* W_in  = (const float*)d_in[4];
    const float* b_in  = (const float*)d_in[5];
    const float* Ws    = (const float*)d_in[6];
    const float* bs    = (const float*)d_in[7];
    float* out = (float*)d_out;

    float *pWtIn;
    uint32_t *pX0b, *pXb, *pYb, *pWtb;
    cudaGetSymbolAddress((void**)&pWtIn, g_WtIn);
    cudaGetSymbolAddress((void**)&pX0b,  g_X0b);
    cudaGetSymbolAddress((void**)&pXb,   g_Xb);
    cudaGetSymbolAddress((void**)&pYb,   g_Yb);
    cudaGetSymbolAddress((void**)&pWtb,  g_Wtb);

    cudaFuncSetAttribute(mma_gemm_in_kernel,
        cudaFuncAttributeMaxDynamicSharedMemorySize, (int)GEMM32_SMEM);
    cudaFuncSetAttribute(mma_gemm_bf16_kernel,
        cudaFuncAttributeMaxDynamicSharedMemorySize, (int)GEMM16_SMEM);

    // prep: zero d_out + detect mask dtype + weight transposes
    prep_kernel<<<Bb + 320, dim3(32, 8)>>>((const unsigned int*)mask, out, Ws, W_in);

    // CSR build (uint2 offsets) + mask expand
    dim3 cm_grid(Nn, Gg + 1);
    csr_mask_kernel<<<cm_grid, 256>>>(Adj, mask);

    dim3 ggrid(Hh / 64, Nn / 128, Gg);   // 256 CTAs

    // X0 = relu(xs @ W_in + b_in)  [tf32; fp32 + bf16 copies]
    mma_gemm_in_kernel<<<ggrid, 256, GEMM32_SMEM>>>(xs, pWtIn, b_in);

    dim3 sp_grid(Nn, Gg);
    const uint32_t* xin = pX0b;
    for (int i = 0; i < Ll; i++) {
        mma_gemm_bf16_kernel<<<ggrid, 256, GEMM16_SMEM>>>(
            xin, pWtb + (long)i * Hh * Hh / 2, pYb);
        if (i < Ll - 1)
            spmm_kernel<false><<<sp_grid, 128>>>(bs + (long)i * Hh);
        else
            spmm_kernel<true><<<sp_grid, 128>>>(bs + (long)i * Hh);
        xin = pXb;
    }

    dim3 mm_grid(Bb, Nn / 128);
    masked_mean_kernel<<<mm_grid, Hh>>>(graph, out);
}

// round 14
// speedup vs baseline: 1.5679x; 1.0586x over previous
#include <cuda_runtime.h>
#include <cuda_bf16.h>
#include <cstdint>

// Problem constants
#define Gg 8
#define Nn 1024
#define Ff 128
#define Hh 256
#define Ll 4
#define Bb 64
#define CAP 128
#define GHALF (Gg / 2)

// ---------------- scratch (device globals) ----------------------------------
__device__ __align__(16) float    g_X0 [Gg * Nn * Hh];          // fp32 residual
__device__ __align__(16) uint32_t g_X0b[Gg * Nn * Hh / 2];      // bf16x2 copy of X0
__device__ __align__(16) float    g_X  [Gg * Nn * Hh];          // fp32 final x
__device__ __align__(16) uint32_t g_Xb [Gg * Nn * Hh / 2];      // bf16x2 inter-layer x
__device__ __align__(16) uint32_t g_Yb [Gg * Nn * Hh / 2];      // bf16x2 Y = x @ W
__device__ __align__(16) uint32_t g_Wtb[Ll * Hh * Hh / 2];      // bf16x2 Ws^T [l][n][k]
__device__ __align__(16) float    g_WtIn[Hh * Ff];              // W_in^T (tf32-rounded)
__device__ __align__(16) int      g_coff[(long)Gg * Nn * CAP];  // precomputed col*64 (uint2 idx)
__device__ __align__(16) float    g_vals[(long)Gg * Nn * CAP];
__device__ int   g_nnz[Gg * Nn];
__device__ float g_maskf[Bb * Nn];
__device__ float g_cnt[Bb];
__device__ int   g_mask_mode;

// ---------------- helpers ----------------------------------------------------
__device__ __forceinline__ float f2tf32(float x) {
    uint32_t r;
    asm("cvt.rna.tf32.f32 %0, %1;" : "=r"(r) : "f"(x));
    return __uint_as_float(r);
}
__device__ __forceinline__ uint32_t frag_tf32(float x) {
    uint32_t r;
    asm("cvt.rna.tf32.f32 %0, %1;" : "=r"(r) : "f"(x));
    return r;
}

__device__ __forceinline__ void mma_tf32(float& c0, float& c1, float& c2, float& c3,
                                         uint32_t a0, uint32_t a1, uint32_t a2, uint32_t a3,
                                         uint32_t b0, uint32_t b1) {
    asm volatile(
        "mma.sync.aligned.m16n8k8.row.col.f32.tf32.tf32.f32 "
        "{%0,%1,%2,%3}, {%4,%5,%6,%7}, {%8,%9}, {%0,%1,%2,%3};"
        : "+f"(c0), "+f"(c1), "+f"(c2), "+f"(c3)
        : "r"(a0), "r"(a1), "r"(a2), "r"(a3), "r"(b0), "r"(b1));
}
__device__ __forceinline__ void mma_bf16(float& c0, float& c1, float& c2, float& c3,
                                         uint32_t a0, uint32_t a1, uint32_t a2, uint32_t a3,
                                         uint32_t b0, uint32_t b1) {
    asm volatile(
        "mma.sync.aligned.m16n8k16.row.col.f32.bf16.bf16.f32 "
        "{%0,%1,%2,%3}, {%4,%5,%6,%7}, {%8,%9}, {%0,%1,%2,%3};"
        : "+f"(c0), "+f"(c1), "+f"(c2), "+f"(c3)
        : "r"(a0), "r"(a1), "r"(a2), "r"(a3), "r"(b0), "r"(b1));
}

__device__ __forceinline__ void cp16(void* dst_smem, const void* src) {
    uint32_t d = (uint32_t)__cvta_generic_to_shared(dst_smem);
    asm volatile("cp.async.cg.shared.global [%0], [%1], 16;"
                 :: "r"(d), "l"(src) : "memory");
}
#define CP_COMMIT() asm volatile("cp.async.commit_group;" ::: "memory")
#define CP_WAIT0()  asm volatile("cp.async.wait_group 0;" ::: "memory")

// ---------------- prep: zero d_out + detect mask + weight transposes ---------
__global__ void prep_kernel(const unsigned int* __restrict__ m,
                            float* __restrict__ out,
                            const float* __restrict__ Ws,
                            const float* __restrict__ W_in) {
    const int t = threadIdx.y * 32 + threadIdx.x;
    const int bid = blockIdx.x;

    if (bid < Bb) {
        out[(long)bid * 256 + t] = 0.0f;
        if (bid != 0) return;
        __shared__ int sh_f, sh_b;
        if (t == 0) { sh_f = 0; sh_b = 0; }
        __syncthreads();
        int f = 0, b = 0;
        for (int i = t; i < 16384; i += 256) {
            unsigned int w = m[i];
            if (w == 0x3F800000u) f = 1;
            if (w > 1u && (w & ~0x01010101u) == 0u) b = 1;
        }
        if (f) atomicOr(&sh_f, 1);
        if (b) atomicOr(&sh_b, 1);
        __syncthreads();
        if (t == 0) g_mask_mode = sh_f ? 1 : (sh_b ? 2 : 0);
        return;
    }

    __shared__ float tile[32][33];
    int idx = bid - Bb;
    int z = idx >> 6;           // 0..4
    int rem = idx & 63;
    int bx = rem & 7, by = rem >> 3;
    int x = threadIdx.x, y = threadIdx.y;

    if (z < Ll) {
        const float* src = Ws + (long)z * Hh * Hh;
        __nv_bfloat16* dst = reinterpret_cast<__nv_bfloat16*>(g_Wtb) + (long)z * Hh * Hh;
        int k0 = bx * 32, h0 = by * 32;
        #pragma unroll
        for (int j = 0; j < 32; j += 8)
            tile[y + j][x] = src[(long)(k0 + y + j) * Hh + h0 + x];
        __syncthreads();
        #pragma unroll
        for (int j = 0; j < 32; j += 8)
            dst[(long)(h0 + y + j) * Hh + k0 + x] = __float2bfloat16(tile[x][y + j]);
    } else {
        if (bx >= Ff / 32) return;
        int k0 = bx * 32, h0 = by * 32;
        #pragma unroll
        for (int j = 0; j < 32; j += 8)
            tile[y + j][x] = W_in[(long)(k0 + y + j) * Hh + h0 + x];
        __syncthreads();
        #pragma unroll
        for (int j = 0; j < 32; j += 8)
            g_WtIn[(long)(h0 + y + j) * Ff + k0 + x] = f2tf32(tile[x][y + j]);
    }
}

// ---------------- CSR build + mask expand (merged) ---------------------------
__global__ void csr_mask_kernel(const float* __restrict__ Adj,
                                const void* __restrict__ mraw) {
    __shared__ int cnt;
    if (blockIdx.y < Gg) {
        int g = blockIdx.y;
        int n = blockIdx.x;
        long rbase = (long)g * Nn + n;
        const float4* row4 = reinterpret_cast<const float4*>(Adj + rbase * Nn);
        if (threadIdx.x == 0) cnt = 0;
        __syncthreads();
        float4 v4 = row4[threadIdx.x];
        int mbase = threadIdx.x * 4;
        #pragma unroll
        for (int c = 0; c < 4; c++) {
            float v = (c == 0) ? v4.x : (c == 1) ? v4.y : (c == 2) ? v4.z : v4.w;
            if (v != 0.0f) {
                int p = atomicAdd(&cnt, 1);
                if (p < CAP) {
                    g_coff[rbase * CAP + p] = (mbase + c) * 64;
                    g_vals[rbase * CAP + p] = v;
                }
            }
        }
        __syncthreads();
        if (threadIdx.x == 0) g_nnz[rbase] = cnt < CAP ? cnt : CAP;
    } else {
        int b = blockIdx.x;
        if (b >= Bb) return;
        int mode = g_mask_mode;
        if (threadIdx.x == 0) cnt = 0;
        __syncthreads();
        int local = 0;
        for (int n = threadIdx.x; n < Nn; n += blockDim.x) {
            long idx = (long)b * Nn + n;
            bool on;
            if (mode == 1)      on = ((const float*)mraw)[idx] != 0.0f;
            else if (mode == 2) on = ((const unsigned char*)mraw)[idx] != 0;
            else                on = ((const int*)mraw)[idx] != 0;
            g_maskf[idx] = on ? 1.0f : 0.0f;
            local += on ? 1 : 0;
        }
        atomicAdd(&cnt, local);
        __syncthreads();
        if (threadIdx.x == 0) g_cnt[b] = (float)(cnt < 1 ? 1 : cnt);
    }
}

// ---------------- single-shot tf32 input GEMM (fp32 A), 128x64, full-K -------
#define PITCH 132
#define GEMM32_SMEM ((128 + 64) * PITCH * sizeof(float))

__global__ __launch_bounds__(256)
void mma_gemm_in_kernel(const float* __restrict__ A,
                        const float* __restrict__ Bt,
                        const float* __restrict__ bias,
                        int g0) {
    constexpr int KDIM = Ff;
    extern __shared__ float sh[];
    float* As = sh;
    float* Bs = sh + 128 * PITCH;

    const int t = threadIdx.x;
    const int wid = t >> 5, lane = t & 31;
    const int gid = lane >> 2, tig = lane & 3;
    const int wy = wid >> 1, wx = wid & 1;
    const int col0 = blockIdx.x * 64;
    const int row0 = blockIdx.y * 128;
    const int g = blockIdx.z + g0;

    const float* Ag = A + ((long)g * Nn + row0) * KDIM;
    float* Cg = g_X0 + ((long)g * Nn + row0) * Hh;
    uint32_t* Cb = g_X0b + ((long)g * Nn + row0) * (Hh / 2);

    #pragma unroll
    for (int i = 0; i < 16; i++) {
        int f = t + i * 256;
        int row = f >> 5, c4 = f & 31;
        cp16(&As[row * PITCH + c4 * 4], &Ag[(long)row * KDIM + c4 * 4]);
    }
    #pragma unroll
    for (int i = 0; i < 8; i++) {
        int f = t + i * 256;
        int row = f >> 5, c4 = f & 31;
        cp16(&Bs[row * PITCH + c4 * 4], &Bt[(long)(col0 + row) * KDIM + c4 * 4]);
    }
    CP_COMMIT();
    CP_WAIT0();
    __syncthreads();

    float acc[2][4][4] = {};
    #pragma unroll
    for (int c = 0; c < KDIM / 32; c++) {
        #pragma unroll
        for (int ks = 0; ks < 4; ks++) {
            const int kk = c * 32 + ks * 8 + tig;
            uint32_t a[2][4];
            #pragma unroll
            for (int mt = 0; mt < 2; mt++) {
                int mr = wy * 32 + mt * 16 + gid;
                a[mt][0] = frag_tf32(As[(mr    ) * PITCH + kk]);
                a[mt][1] = frag_tf32(As[(mr + 8) * PITCH + kk]);
                a[mt][2] = frag_tf32(As[(mr    ) * PITCH + kk + 4]);
                a[mt][3] = frag_tf32(As[(mr + 8) * PITCH + kk + 4]);
            }
            uint32_t b[4][2];
            #pragma unroll
            for (int nt = 0; nt < 4; nt++) {
                int nr = wx * 32 + nt * 8 + gid;
                b[nt][0] = __float_as_uint(Bs[nr * PITCH + kk]);
                b[nt][1] = __float_as_uint(Bs[nr * PITCH + kk + 4]);
            }
            #pragma unroll
            for (int mt = 0; mt < 2; mt++)
                #pragma unroll
                for (int nt = 0; nt < 4; nt++)
                    mma_tf32(acc[mt][nt][0], acc[mt][nt][1],
                             acc[mt][nt][2], acc[mt][nt][3],
                             a[mt][0], a[mt][1], a[mt][2], a[mt][3],
                             b[nt][0], b[nt][1]);
        }
    }

    #pragma unroll
    for (int mt = 0; mt < 2; mt++) {
        int r = wy * 32 + mt * 16 + gid;
        #pragma unroll
        for (int nt = 0; nt < 4; nt++) {
            int cc = col0 + wx * 32 + nt * 8 + 2 * tig;
            float b0 = bias[cc], b1 = bias[cc + 1];
            float v0 = fmaxf(acc[mt][nt][0] + b0, 0.f);
            float v1 = fmaxf(acc[mt][nt][1] + b1, 0.f);
            float v2 = fmaxf(acc[mt][nt][2] + b0, 0.f);
            float v3 = fmaxf(acc[mt][nt][3] + b1, 0.f);
            *reinterpret_cast<float2*>(&Cg[(long)r * Hh + cc]) = make_float2(v0, v1);
            *reinterpret_cast<float2*>(&Cg[(long)(r + 8) * Hh + cc]) = make_float2(v2, v3);
            __nv_bfloat162 p0 = __float22bfloat162_rn(make_float2(v0, v1));
            __nv_bfloat162 p1 = __float22bfloat162_rn(make_float2(v2, v3));
            Cb[(long)r * (Hh / 2) + cc / 2]       = *reinterpret_cast<uint32_t*>(&p0);
            Cb[(long)(r + 8) * (Hh / 2) + cc / 2] = *reinterpret_cast<uint32_t*>(&p1);
        }
    }
}

// ---------------- single-shot bf16 layer GEMM: Yb = Xb @ Wtb^T ----------------
#define GEMM16_SMEM ((128 + 64) * PITCH * sizeof(uint32_t))

__global__ __launch_bounds__(256)
void mma_gemm_bf16_kernel(const uint32_t* __restrict__ A,
                          const uint32_t* __restrict__ Bt,
                          uint32_t* __restrict__ Yout,
                          int g0) {
    constexpr int KW = Hh / 2;
    extern __shared__ uint32_t shw[];
    uint32_t* As = shw;
    uint32_t* Bs = shw + 128 * PITCH;

    const int t = threadIdx.x;
    const int wid = t >> 5, lane = t & 31;
    const int gid = lane >> 2, tig = lane & 3;
    const int wy = wid >> 1, wx = wid & 1;
    const int col0 = blockIdx.x * 64;
    const int row0 = blockIdx.y * 128;
    const int g = blockIdx.z + g0;

    const uint32_t* Ag = A + ((long)g * Nn + row0) * KW;
    uint32_t* Yb = Yout + ((long)g * Nn + row0) * (Hh / 2);

    #pragma unroll
    for (int i = 0; i < 16; i++) {
        int f = t + i * 256;
        int row = f >> 5, c4 = f & 31;
        cp16(&As[row * PITCH + c4 * 4], &Ag[(long)row * KW + c4 * 4]);
    }
    #pragma unroll
    for (int i = 0; i < 8; i++) {
        int f = t + i * 256;
        int row = f >> 5, c4 = f & 31;
        cp16(&Bs[row * PITCH + c4 * 4], &Bt[(long)(col0 + row) * KW + c4 * 4]);
    }
    CP_COMMIT();
    CP_WAIT0();
    __syncthreads();

    float acc[2][4][4] = {};
    #pragma unroll
    for (int c = 0; c < 8; c++) {
        #pragma unroll
        for (int ks = 0; ks < 2; ks++) {
            const int kw = c * 16 + ks * 8 + tig;
            uint32_t a[2][4];
            #pragma unroll
            for (int mt = 0; mt < 2; mt++) {
                int mr = wy * 32 + mt * 16 + gid;
                a[mt][0] = As[(mr    ) * PITCH + kw];
                a[mt][1] = As[(mr + 8) * PITCH + kw];
                a[mt][2] = As[(mr    ) * PITCH + kw + 4];
                a[mt][3] = As[(mr + 8) * PITCH + kw + 4];
            }
            uint32_t b[4][2];
            #pragma unroll
            for (int nt = 0; nt < 4; nt++) {
                int nr = wx * 32 + nt * 8 + gid;
                b[nt][0] = Bs[nr * PITCH + kw];
                b[nt][1] = Bs[nr * PITCH + kw + 4];
            }
            #pragma unroll
            for (int mt = 0; mt < 2; mt++)
                #pragma unroll
                for (int nt = 0; nt < 4; nt++)
                    mma_bf16(acc[mt][nt][0], acc[mt][nt][1],
                             acc[mt][nt][2], acc[mt][nt][3],
                             a[mt][0], a[mt][1], a[mt][2], a[mt][3],
                             b[nt][0], b[nt][1]);
        }
    }

    #pragma unroll
    for (int mt = 0; mt < 2; mt++) {
        int r = wy * 32 + mt * 16 + gid;
        #pragma unroll
        for (int nt = 0; nt < 4; nt++) {
            int cc = col0 + wx * 32 + nt * 8 + 2 * tig;
            __nv_bfloat162 p0 = __float22bfloat162_rn(
                make_float2(acc[mt][nt][0], acc[mt][nt][1]));
            __nv_bfloat162 p1 = __float22bfloat162_rn(
                make_float2(acc[mt][nt][2], acc[mt][nt][3]));
            Yb[(long)r * (Hh / 2) + cc / 2]       = *reinterpret_cast<uint32_t*>(&p0);
            Yb[(long)(r + 8) * (Hh / 2) + cc / 2] = *reinterpret_cast<uint32_t*>(&p1);
        }
    }
}

// ---------------- SpMM: X = act(A_sparse @ Yb + bias) ------------------------
template<bool LAST>
__global__ __launch_bounds__(128)
void spmm_kernel(const float* __restrict__ bias, int g0) {
    int g = blockIdx.y + g0;
    int n = blockIdx.x;
    int t = threadIdx.x;
    int grp = t >> 6, u = t & 63;
    int lane = t & 31, wid = t >> 5;
    long rbase = (long)g * Nn + n;
    int nnz = g_nnz[rbase];

    __shared__ int   soff[CAP];
    __shared__ float sval[CAP];
    for (int j = t; j < nnz; j += 128) {
        soff[j] = g_coff[rbase * CAP + j];
        sval[j] = g_vals[rbase * CAP + j];
    }
    __syncthreads();

    const uint2* Yu = reinterpret_cast<const uint2*>(
        g_Yb + (long)g * Nn * (Hh / 2)) + u;
    float a0 = 0.f, a1 = 0.f, a2 = 0.f, a3 = 0.f;
    int j = grp;
    for (; j + 14 < nnz; j += 16) {
        uint2 w[8];
        #pragma unroll
        for (int q = 0; q < 8; q++)
            w[q] = Yu[soff[j + 2 * q]];
        #pragma unroll
        for (int q = 0; q < 8; q++) {
            float s = sval[j + 2 * q];
            float2 f0 = __bfloat1622float2(*reinterpret_cast<__nv_bfloat162*>(&w[q].x));
            float2 f1 = __bfloat1622float2(*reinterpret_cast<__nv_bfloat162*>(&w[q].y));
            a0 += s * f0.x; a1 += s * f0.y;
            a2 += s * f1.x; a3 += s * f1.y;
        }
    }
    for (; j < nnz; j += 2) {
        uint2 w = Yu[soff[j]];
        float s = sval[j];
        float2 f0 = __bfloat1622float2(*reinterpret_cast<__nv_bfloat162*>(&w.x));
        float2 f1 = __bfloat1622float2(*reinterpret_cast<__nv_bfloat162*>(&w.y));
        a0 += s * f0.x; a1 += s * f0.y;
        a2 += s * f1.x; a3 += s * f1.y;
    }

    __shared__ float4 red[64];
    if (grp == 1) red[u] = make_float4(a0, a1, a2, a3);
    __syncthreads();
    if (grp == 0) {
        float4 r = red[u];
        a0 += r.x; a1 += r.y; a2 += r.z; a3 += r.w;
    }

    if (!LAST) {
        if (grp == 0) {
            float4 bv = *reinterpret_cast<const float4*>(&bias[4 * u]);
            float v0 = fmaxf(a0 + bv.x, 0.f);
            float v1 = fmaxf(a1 + bv.y, 0.f);
            float v2 = fmaxf(a2 + bv.z, 0.f);
            float v3 = fmaxf(a3 + bv.w, 0.f);
            __nv_bfloat162 p0 = __float22bfloat162_rn(make_float2(v0, v1));
            __nv_bfloat162 p1 = __float22bfloat162_rn(make_float2(v2, v3));
            uint2 o;
            o.x = *reinterpret_cast<uint32_t*>(&p0);
            o.y = *reinterpret_cast<uint32_t*>(&p1);
            reinterpret_cast<uint2*>(g_Xb)[rbase * 64 + u] = o;
        }
    } else {
        float v0 = 0.f, v1 = 0.f, v2 = 0.f, v3 = 0.f;
        float m = -1e30f;
        if (grp == 0) {
            float4 bv = *reinterpret_cast<const float4*>(&bias[4 * u]);
            v0 = a0 + bv.x; v1 = a1 + bv.y; v2 = a2 + bv.z; v3 = a3 + bv.w;
            m = fmaxf(fmaxf(v0, v1), fmaxf(v2, v3));
        }
        #pragma unroll
        for (int off = 16; off > 0; off >>= 1)
            m = fmaxf(m, __shfl_xor_sync(0xFFFFFFFFu, m, off));
        __shared__ float smax[4], ssum[4];
        if (lane == 0) smax[wid] = m;
        __syncthreads();
        m = fmaxf(smax[0], smax[1]);
        float e0 = 0.f, e1 = 0.f, e2 = 0.f, e3 = 0.f, s = 0.f;
        if (grp == 0) {
            e0 = expf(v0 - m); e1 = expf(v1 - m);
            e2 = expf(v2 - m); e3 = expf(v3 - m);
            s = (e0 + e1) + (e2 + e3);
        }
        #pragma unroll
        for (int off = 16; off > 0; off >>= 1)
            s += __shfl_xor_sync(0xFFFFFFFFu, s, off);
        if (lane == 0) ssum[wid] = s;
        __syncthreads();
        s = ssum[0] + ssum[1];
        if (grp == 0) {
            float inv = 1.0f / s;
            float4 x0 = reinterpret_cast<const float4*>(g_X0)[rbase * 64 + u];
            reinterpret_cast<float4*>(g_X)[rbase * 64 + u] =
                make_float4(e0 * inv + x0.x, e1 * inv + x0.y,
                            e2 * inv + x0.z, e3 * inv + x0.w);
        }
    }
}

// ---------------- per-sample masked mean -------------------------------------
__global__ void masked_mean_kernel(const int* __restrict__ graph,
                                   float* __restrict__ out) {
    int b = blockIdx.x;
    int chunk = blockIdx.y;
    int h = threadIdx.x;
    int g = graph[b];
    const float* xg = g_X + ((long)g * Nn + chunk * 128) * Hh;
    const float* mb = g_maskf + (long)b * Nn + chunk * 128;
    float acc = 0.f;
    #pragma unroll 4
    for (int n = 0; n < 128; n++) {
        float mv = mb[n];
        if (mv != 0.f) acc += xg[(long)n * Hh + h];
    }
    atomicAdd(&out[(long)b * Hh + h], acc / g_cnt[b]);
}

// ---------------- launch -----------------------------------------------------
extern "C" void kernel_launch(void* const* d_in, const int* in_sizes, int n_in,
                              void* d_out, int out_size) {
    const int*   graph = (const int*)  d_in[0];
    const void*  mask  =               d_in[1];
    const float* xs    = (const float*)d_in[2];
    const float* Adj   = (const float*)d_in[3];
    const float* W_in  = (const float*)d_in[4];
    const float* b_in  = (const float*)d_in[5];
    const float* Ws    = (const float*)d_in[6];
    const float* bs    = (const float*)d_in[7];
    float* out = (float*)d_out;

    float *pWtIn;
    uint32_t *pX0b, *pXb, *pYb, *pWtb;
    cudaGetSymbolAddress((void**)&pWtIn, g_WtIn);
    cudaGetSymbolAddress((void**)&pX0b,  g_X0b);
    cudaGetSymbolAddress((void**)&pXb,   g_Xb);
    cudaGetSymbolAddress((void**)&pYb,   g_Yb);
    cudaGetSymbolAddress((void**)&pWtb,  g_Wtb);

    // one-time stream/event setup (first call is the uncaptured correctness run)
    static cudaStream_t s1 = nullptr, s2 = nullptr;
    static cudaEvent_t evRoot = nullptr, evA = nullptr, evB = nullptr;
    if (s1 == nullptr) {
        cudaStreamCreateWithFlags(&s1, cudaStreamNonBlocking);
        cudaStreamCreateWithFlags(&s2, cudaStreamNonBlocking);
        cudaEventCreateWithFlags(&evRoot, cudaEventDisableTiming);
        cudaEventCreateWithFlags(&evA, cudaEventDisableTiming);
        cudaEventCreateWithFlags(&evB, cudaEventDisableTiming);
        cudaFuncSetAttribute(mma_gemm_in_kernel,
            cudaFuncAttributeMaxDynamicSharedMemorySize, (int)GEMM32_SMEM);
        cudaFuncSetAttribute(mma_gemm_bf16_kernel,
            cudaFuncAttributeMaxDynamicSharedMemorySize, (int)GEMM16_SMEM);
    }

    // prep + CSR on the default stream (shared by both halves)
    prep_kernel<<<Bb + 320, dim3(32, 8)>>>((const unsigned int*)mask, out, Ws, W_in);
    dim3 cm_grid(Nn, Gg + 1);
    csr_mask_kernel<<<cm_grid, 256>>>(Adj, mask);

    // fork: two independent half-chains over graphs [0,4) and [4,8)
    cudaEventRecord(evRoot, 0);
    cudaStreamWaitEvent(s1, evRoot, 0);
    cudaStreamWaitEvent(s2, evRoot, 0);

    dim3 hgrid(Hh / 64, Nn / 128, GHALF);   // 128 CTAs per half
    dim3 hsp(Nn, GHALF);

    cudaStream_t streams[2] = { s1, s2 };
    for (int h = 0; h < 2; h++) {
        cudaStream_t st = streams[h];
        int g0 = h * GHALF;
        mma_gemm_in_kernel<<<hgrid, 256, GEMM32_SMEM, st>>>(xs, pWtIn, b_in, g0);
        const uint32_t* xin = pX0b;
        for (int i = 0; i < Ll; i++) {
            mma_gemm_bf16_kernel<<<hgrid, 256, GEMM16_SMEM, st>>>(
                xin, pWtb + (long)i * Hh * Hh / 2, pYb, g0);
            if (i < Ll - 1)
                spmm_kernel<false><<<hsp, 128, 0, st>>>(bs + (long)i * Hh, g0);
            else
                spmm_kernel<true><<<hsp, 128, 0, st>>>(bs + (long)i * Hh, g0);
            xin = pXb;
        }
    }

    // join
    cudaEventRecord(evA, s1);
    cudaEventRecord(evB, s2);
    cudaStreamWaitEvent(0, evA, 0);
    cudaStreamWaitEvent(0, evB, 0);

    dim3 mm_grid(Bb, Nn / 128);
    masked_mean_kernel<<<mm_grid, Hh>>>(graph, out);
}